// round 13
// baseline (speedup 1.0000x reference)
#include <cuda_runtime.h>
#include <cuda_bf16.h>
#include <math.h>
#include <stdint.h>

#define BB 2
#define SSL 1024
#define NTOK 2048
#define DD 512
#define HHN 8
#define HHI 4
#define DII 64
#define FFD 2048
#define EE 8
#define VV 32000
#define KTOP 256
#define NEGV (-1e9f)
#define EPSV 1e-5f
#define LLN 2
#define SCALE 0.125f

__device__ float g_x[NTOK*DD];
__device__ float g_h[NTOK*DD];
__device__ float g_m[NTOK*DD];
__device__ float g_q[NTOK*DD];
__device__ float g_k[NTOK*DD];
__device__ float g_v[NTOK*DD];
__device__ float g_moe[NTOK*DD];
__device__ float g_mask[(size_t)BB*SSL*SSL];
__device__ int g_ecount[EE];
__device__ int g_elist[EE*NTOK];
__device__ float g_egate[EE*NTOK];
__device__ alignas(16) __nv_bfloat16 g_hhi[NTOK*DD];
__device__ alignas(16) __nv_bfloat16 g_hlo[NTOK*DD];
__device__ alignas(16) __nv_bfloat16 g_mhi[NTOK*DD];
__device__ alignas(16) __nv_bfloat16 g_mlo[NTOK*DD];
__device__ alignas(16) __nv_bfloat16 g_aohi[NTOK*DD];
__device__ alignas(16) __nv_bfloat16 g_aolo[NTOK*DD];
__device__ alignas(16) float g_qi[NTOK*HHI*DII];
__device__ alignas(16) float g_ki[NTOK*HHI*DII];
__device__ alignas(16) __nv_bfloat16 g_owThi[(size_t)VV*DD];
__device__ alignas(16) __nv_bfloat16 g_owTlo[(size_t)VV*DD];
__device__ alignas(16) __nv_bfloat16 g_w1Thi[(size_t)LLN*EE*FFD*DD];
__device__ alignas(16) __nv_bfloat16 g_w1Tlo[(size_t)LLN*EE*FFD*DD];
__device__ alignas(16) __nv_bfloat16 g_w2Thi[(size_t)LLN*EE*DD*FFD];
__device__ alignas(16) __nv_bfloat16 g_w2Tlo[(size_t)LLN*EE*DD*FFD];
__device__ alignas(16) __nv_bfloat16 g_h1hi[(size_t)EE*NTOK*FFD];
__device__ alignas(16) __nv_bfloat16 g_h1lo[(size_t)EE*NTOK*FFD];
__device__ alignas(16) __nv_bfloat16 g_wqThi[LLN*DD*DD];
__device__ alignas(16) __nv_bfloat16 g_wqTlo[LLN*DD*DD];
__device__ alignas(16) __nv_bfloat16 g_wkThi[LLN*DD*DD];
__device__ alignas(16) __nv_bfloat16 g_wkTlo[LLN*DD*DD];
__device__ alignas(16) __nv_bfloat16 g_wvThi[LLN*DD*DD];
__device__ alignas(16) __nv_bfloat16 g_wvTlo[LLN*DD*DD];
__device__ alignas(16) __nv_bfloat16 g_woThi[LLN*DD*DD];
__device__ alignas(16) __nv_bfloat16 g_woTlo[LLN*DD*DD];
__device__ alignas(16) __nv_bfloat16 g_iqThi[LLN*HHI*DII*DD];
__device__ alignas(16) __nv_bfloat16 g_iqTlo[LLN*HHI*DII*DD];
__device__ alignas(16) __nv_bfloat16 g_ikThi[LLN*HHI*DII*DD];
__device__ alignas(16) __nv_bfloat16 g_ikTlo[LLN*HHI*DII*DD];

__device__ __forceinline__ float gelu_tanh(float x){
    float x3 = x*x*x;
    return 0.5f*x*(1.f + tanhf(0.7978845608028654f*(x + 0.044715f*x3)));
}

__global__ void k_embed(const int* __restrict__ ids, const float* __restrict__ tok, const float* __restrict__ pos){
    int n=blockIdx.x, t=threadIdx.x;
    g_x[(size_t)n*DD+t] = tok[(size_t)ids[n]*DD+t] + pos[(size_t)(n%SSL)*DD+t];
}

__global__ __launch_bounds__(256) void k_ln(float* __restrict__ in, const float* __restrict__ g,
        const float* __restrict__ b, float* __restrict__ out,
        __nv_bfloat16* __restrict__ hi, __nv_bfloat16* __restrict__ lo,
        const float* __restrict__ radd, int* __restrict__ ecz){
    int r=blockIdx.x, t=threadIdx.x;
    int lane=t&31, wid=t>>5;
    __shared__ float red1[8], red2[8];
    if(ecz && r==0 && t<EE) ecz[t]=0;
    float v0=in[(size_t)r*DD+t], v1=in[(size_t)r*DD+t+256];
    if(radd){
        v0 += radd[(size_t)r*DD+t];
        v1 += radd[(size_t)r*DD+t+256];
        in[(size_t)r*DD+t]=v0;
        in[(size_t)r*DD+t+256]=v1;
    }
    float s=v0+v1;
    #pragma unroll
    for(int off=16;off>0;off>>=1) s+=__shfl_xor_sync(0xffffffffu,s,off);
    if(lane==0) red1[wid]=s;
    __syncthreads();
    float mu=(red1[0]+red1[1]+red1[2]+red1[3]+red1[4]+red1[5]+red1[6]+red1[7])*(1.0f/DD);
    float d0=v0-mu, d1=v1-mu;
    float s2=d0*d0+d1*d1;
    #pragma unroll
    for(int off=16;off>0;off>>=1) s2+=__shfl_xor_sync(0xffffffffu,s2,off);
    if(lane==0) red2[wid]=s2;
    __syncthreads();
    float var=(red2[0]+red2[1]+red2[2]+red2[3]+red2[4]+red2[5]+red2[6]+red2[7])*(1.0f/DD);
    float rs=rsqrtf(var+EPSV);
    float o0=d0*rs*g[t]+b[t];
    float o1=d1*rs*g[t+256]+b[t+256];
    out[(size_t)r*DD+t]=o0;
    out[(size_t)r*DD+t+256]=o1;
    if(hi){
        __nv_bfloat16 h0=__float2bfloat16(o0), h1=__float2bfloat16(o1);
        hi[(size_t)r*DD+t]=h0;
        hi[(size_t)r*DD+t+256]=h1;
        lo[(size_t)r*DD+t]=__float2bfloat16(o0-__bfloat162float(h0));
        lo[(size_t)r*DD+t+256]=__float2bfloat16(o1-__bfloat162float(h1));
    }
}

__global__ __launch_bounds__(256) void k_transcvtB(const float* __restrict__ W,
        __nv_bfloat16* __restrict__ Thi, __nv_bfloat16* __restrict__ Tlo, int K, int N){
    int z=blockIdx.z;
    W   += (size_t)z*K*N;
    Thi += (size_t)z*N*K;
    Tlo += (size_t)z*N*K;
    __shared__ float t[32][66];
    int n0=blockIdx.x*32, k0=blockIdx.y*64;
    int lane=threadIdx.x&31, wid=threadIdx.x>>5;
    #pragma unroll
    for(int i=0;i<8;i++){
        int kk=wid*8+i;
        t[lane][kk]=W[(size_t)(k0+kk)*N + n0+lane];
    }
    __syncthreads();
    #pragma unroll
    for(int j=0;j<4;j++){
        int n=wid*4+j;
        float2 ab=*(float2*)&t[n][2*lane];
        __nv_bfloat16 ha=__float2bfloat16(ab.x), hb=__float2bfloat16(ab.y);
        uint32_t hw=(uint32_t)__bfloat16_as_ushort(ha) | ((uint32_t)__bfloat16_as_ushort(hb)<<16);
        __nv_bfloat16 la=__float2bfloat16(ab.x-__bfloat162float(ha));
        __nv_bfloat16 lb=__float2bfloat16(ab.y-__bfloat162float(hb));
        uint32_t lw=(uint32_t)__bfloat16_as_ushort(la) | ((uint32_t)__bfloat16_as_ushort(lb)<<16);
        *(uint32_t*)(Thi + (size_t)(n0+n)*K + k0 + 2*lane)=hw;
        *(uint32_t*)(Tlo + (size_t)(n0+n)*K + k0 + 2*lane)=lw;
    }
}

// ================= HMMA primitives =================
__device__ __forceinline__ uint32_t smem_u32(const void* p){
    uint32_t a;
    asm("{ .reg .u64 t; cvta.to.shared.u64 t, %1; cvt.u32.u64 %0, t; }" : "=r"(a) : "l"(p));
    return a;
}
__device__ __forceinline__ void ldsm4(uint32_t (&r)[4], uint32_t a){
    asm volatile("ldmatrix.sync.aligned.m8n8.x4.shared.b16 {%0,%1,%2,%3}, [%4];"
        : "=r"(r[0]),"=r"(r[1]),"=r"(r[2]),"=r"(r[3]) : "r"(a));
}
__device__ __forceinline__ void ldsm2(uint32_t (&r)[2], uint32_t a){
    asm volatile("ldmatrix.sync.aligned.m8n8.x2.shared.b16 {%0,%1}, [%2];"
        : "=r"(r[0]),"=r"(r[1]) : "r"(a));
}
__device__ __forceinline__ void mma16816(float (&c)[4], const uint32_t (&a)[4], const uint32_t (&b)[2]){
    asm volatile("mma.sync.aligned.m16n8k16.row.col.f32.bf16.bf16.f32 "
        "{%0,%1,%2,%3}, {%4,%5,%6,%7}, {%8,%9}, {%0,%1,%2,%3};"
        : "+f"(c[0]),"+f"(c[1]),"+f"(c[2]),"+f"(c[3])
        : "r"(a[0]),"r"(a[1]),"r"(a[2]),"r"(a[3]), "r"(b[0]),"r"(b[1]));
}
__device__ __forceinline__ void cpasync16(uint32_t dst, const void* src){
    asm volatile("{ .reg .u64 g; cvta.to.global.u64 g, %1; cp.async.ca.shared.global [%0], [g], 16; }"
        :: "r"(dst), "l"(src));
}
#define HS_BUF 24576
#define HS_TILE 6144
#define HS_TOTAL 49664

// cp.async double-buffered 128x128 mainloop
__device__ __forceinline__ void hmma_main(char* sm, const int* rowidx,
    const __nv_bfloat16* __restrict__ Ahi, const __nv_bfloat16* __restrict__ Alo, int sA,
    const __nv_bfloat16* __restrict__ Bhi, const __nv_bfloat16* __restrict__ Blo, int sB,
    int col0, int K, float (&acc)[4][4][4])
{
    int tid=threadIdx.x, lane=tid&31, warp=tid>>5;
    int wm=warp>>2, wn=warp&3;
    uint32_t smb = smem_u32(sm);
    #pragma unroll
    for(int i=0;i<4;i++)
        #pragma unroll
        for(int j=0;j<4;j++)
            #pragma unroll
            for(int q=0;q<4;q++) acc[i][j][q]=0.f;

    int ltile[4], lrow[4], lhalf[4];
    #pragma unroll
    for(int t=0;t<4;t++){
        int i = tid + t*256;
        ltile[t]=i>>8; lrow[t]=(i&255)>>1; lhalf[t]=(i&1)*8;
    }
    const int NS = K>>4;
    int lb = lane&15;
    uint32_t boff = (uint32_t)((wn*32 + (lb&7))*48 + ((lb&8)?16:0));
    uint32_t aoff = (uint32_t)((wm*64 + (lane&7) + ((lane&8)?8:0))*48 + ((lane&16)?16:0));

    auto load_stage = [&](int s, int b){
        int k0 = s<<4;
        #pragma unroll
        for(int t=0;t<4;t++){
            const __nv_bfloat16* src;
            int row=lrow[t];
            if(ltile[t]==0)      src = Ahi + (size_t)rowidx[row]*sA;
            else if(ltile[t]==1) src = Alo + (size_t)rowidx[row]*sA;
            else if(ltile[t]==2) src = Bhi + (size_t)(col0+row)*sB;
            else                 src = Blo + (size_t)(col0+row)*sB;
            cpasync16(smb + b*HS_BUF + ltile[t]*HS_TILE + lrow[t]*48 + lhalf[t]*2,
                      src + k0 + lhalf[t]);
        }
        asm volatile("cp.async.commit_group;" ::: "memory");
    };
    load_stage(0,0);
    asm volatile("cp.async.wait_group 0;" ::: "memory");
    __syncthreads();
    for(int s=0;s<NS;s++){
        int b=s&1;
        if(s+1<NS) load_stage(s+1, b^1);
        uint32_t base = smb + b*HS_BUF;
        uint32_t bh[4][2], bl[4][2];
        #pragma unroll
        for(int j=0;j<4;j++){
            ldsm2(bh[j], base + 2*HS_TILE + boff + j*8*48);
            ldsm2(bl[j], base + 3*HS_TILE + boff + j*8*48);
        }
        #pragma unroll
        for(int i=0;i<4;i++){
            uint32_t a[4];
            ldsm4(a, base + aoff + i*16*48);
            #pragma unroll
            for(int j=0;j<4;j++){ mma16816(acc[i][j], a, bh[j]); mma16816(acc[i][j], a, bl[j]); }
            ldsm4(a, base + HS_TILE + aoff + i*16*48);
            #pragma unroll
            for(int j=0;j<4;j++) mma16816(acc[i][j], a, bh[j]);
        }
        if(s+1<NS) asm volatile("cp.async.wait_group 0;" ::: "memory");
        __syncthreads();
    }
}

// ===== 128x256 cp.async mainloop (shared by vocab and moe1) =====
#define V_BUF 36864
#define V_TOTAL 73728
#define M1_TOTAL 74240
__device__ __forceinline__ void hmma_main256(char* sm, const int* rowidx,
    const __nv_bfloat16* __restrict__ Ahi, const __nv_bfloat16* __restrict__ Alo, int sA,
    const __nv_bfloat16* __restrict__ Bhi, const __nv_bfloat16* __restrict__ Blo, int sB,
    int col0, int K, float (&acc)[4][8][4])
{
    int tid=threadIdx.x, lane=tid&31, warp=tid>>5;
    int wm=warp>>2, wn=warp&3;
    uint32_t smb = smem_u32(sm);
    #pragma unroll
    for(int i=0;i<4;i++)
        #pragma unroll
        for(int j=0;j<8;j++)
            #pragma unroll
            for(int q=0;q<4;q++) acc[i][j][q]=0.f;

    auto load_stage = [&](int s, int b){
        int k0 = s<<4;
        #pragma unroll
        for(int c=0;c<6;c++){
            int i = tid + c*256;
            const __nv_bfloat16* src; uint32_t dst;
            if(i<512){
                int tile=i>>8, rem=i&255, row=rem>>1, half=(rem&1)*8;
                src = (tile? Alo : Ahi) + (size_t)rowidx[row]*sA + k0 + half;
                dst = smb + b*V_BUF + tile*6144 + row*48 + half*2;
            }else{
                int ii=i-512, tile=ii>>9, rem=ii&511, row=rem>>1, half=(rem&1)*8;
                src = (tile? Blo : Bhi) + (size_t)(col0+row)*sB + k0 + half;
                dst = smb + b*V_BUF + 12288 + tile*12288 + row*48 + half*2;
            }
            cpasync16(dst, src);
        }
        asm volatile("cp.async.commit_group;" ::: "memory");
    };
    load_stage(0,0);
    asm volatile("cp.async.wait_group 0;" ::: "memory");
    __syncthreads();

    int lb = lane&15;
    uint32_t boff = (uint32_t)((wn*64 + (lb&7))*48 + ((lb&8)?16:0));
    uint32_t aoff = (uint32_t)((wm*64 + (lane&7) + ((lane&8)?8:0))*48 + ((lane&16)?16:0));
    const int NS = K>>4;
    for(int s=0;s<NS;s++){
        int b=s&1;
        if(s+1<NS) load_stage(s+1, b^1);
        uint32_t base = smb + b*V_BUF;
        uint32_t bh[8][2], bl[8][2];
        #pragma unroll
        for(int j=0;j<8;j++){
            ldsm2(bh[j], base + 12288 + boff + j*8*48);
            ldsm2(bl[j], base + 24576 + boff + j*8*48);
        }
        #pragma unroll
        for(int i=0;i<4;i++){
            uint32_t a[4];
            ldsm4(a, base + aoff + i*16*48);
            #pragma unroll
            for(int j=0;j<8;j++){ mma16816(acc[i][j], a, bh[j]); mma16816(acc[i][j], a, bl[j]); }
            ldsm4(a, base + 6144 + aoff + i*16*48);
            #pragma unroll
            for(int j=0;j<8;j++) mma16816(acc[i][j], a, bh[j]);
        }
        if(s+1<NS) asm volatile("cp.async.wait_group 0;" ::: "memory");
        __syncthreads();
    }
}

// ---- vocab: 128x256 tile; grid (NTOK/128, VV/256) ----
__global__ __launch_bounds__(256,1) void k_hmma_vocab(const float* __restrict__ ob, float* __restrict__ out){
    extern __shared__ char sm[];
    int* rowidx = (int*)(sm + 2*V_BUF);
    int tid=threadIdx.x;
    int row0=blockIdx.x*128, col0=blockIdx.y*256;
    if(tid<128) rowidx[tid]=row0+tid;
    __syncthreads();
    float acc[4][8][4];
    hmma_main256(sm, rowidx, g_hhi, g_hlo, DD, g_owThi, g_owTlo, DD, col0, DD, acc);
    int lane=tid&31, warp=tid>>5, wm=warp>>2, wn=warp&3;
    #pragma unroll
    for(int i=0;i<4;i++){
        int r0 = row0 + wm*64 + i*16 + (lane>>2);
        #pragma unroll
        for(int j=0;j<8;j++){
            int c = col0 + wn*64 + j*8 + (lane&3)*2;
            float b0=ob[c], b1=ob[c+1];
            out[(size_t)r0*VV + c]       = acc[i][j][0] + b0;
            out[(size_t)r0*VV + c+1]     = acc[i][j][1] + b1;
            out[(size_t)(r0+8)*VV + c]   = acc[i][j][2] + b0;
            out[(size_t)(r0+8)*VV + c+1] = acc[i][j][3] + b1;
        }
    }
}

// ---- MoE1: 128x256 tile, gathered rows, GELU + split-bf16 out; grid (NTOK/128, FFD/256, EE) ----
__global__ __launch_bounds__(256,1) void k_hmma_moe1(const __nv_bfloat16* __restrict__ Whi,
        const __nv_bfloat16* __restrict__ Wlo, const float* __restrict__ B1){
    int e=blockIdx.z, cnt=g_ecount[e], row0=blockIdx.x*128;
    if(row0>=cnt) return;
    extern __shared__ char sm[];
    int* rowidx = (int*)(sm + 2*V_BUF);
    int tid=threadIdx.x;
    int col0=blockIdx.y*256;
    if(tid<128){
        int r=row0+tid;
        rowidx[tid] = (r<cnt)? g_elist[e*NTOK+r] : g_elist[e*NTOK];
    }
    __syncthreads();
    float acc[4][8][4];
    hmma_main256(sm, rowidx, g_mhi, g_mlo, DD,
                 Whi+(size_t)e*FFD*DD, Wlo+(size_t)e*FFD*DD, DD, col0, DD, acc);
    const float* bia = B1 + (size_t)e*FFD;
    int lane=tid&31, warp=tid>>5, wm=warp>>2, wn=warp&3;
    #pragma unroll
    for(int i=0;i<4;i++){
        int r0 = row0 + wm*64 + i*16 + (lane>>2);
        #pragma unroll
        for(int j=0;j<8;j++){
            int c = col0 + wn*64 + j*8 + (lane&3)*2;
            float b0=bia[c], b1=bia[c+1];
            #pragma unroll
            for(int q=0;q<4;q++){
                int r = r0 + (q>=2?8:0);
                if(r>=cnt) continue;
                int cc = c + (q&1);
                float v = gelu_tanh(acc[i][j][q] + ((q&1)?b1:b0));
                __nv_bfloat16 h=__float2bfloat16(v);
                size_t o = ((size_t)e*NTOK + r)*FFD + cc;
                g_h1hi[o]=h; g_h1lo[o]=__float2bfloat16(v-__bfloat162float(h));
            }
        }
    }
}

// ---- generic projection: fp32 out, 3-way batched ----
struct H3 {
    const __nv_bfloat16 *h0,*l0,*h1,*l1,*h2,*l2;
    const float *c0,*c1,*c2;
    float *o0,*o1,*o2;
};
__global__ __launch_bounds__(256,1) void k_hmma_proj(H3 p, int N){
    extern __shared__ char sm[];
    int* rowidx = (int*)(sm + 2*HS_BUF);
    int tid=threadIdx.x;
    int row0=blockIdx.y*128, col0=blockIdx.x*128;
    const __nv_bfloat16 *Bh,*Bl; const float* bias; float* out;
    if(blockIdx.z==0){Bh=p.h0;Bl=p.l0;bias=p.c0;out=p.o0;}
    else if(blockIdx.z==1){Bh=p.h1;Bl=p.l1;bias=p.c1;out=p.o1;}
    else {Bh=p.h2;Bl=p.l2;bias=p.c2;out=p.o2;}
    if(tid<128) rowidx[tid]=row0+tid;
    __syncthreads();
    float acc[4][4][4];
    hmma_main(sm, rowidx, g_hhi, g_hlo, DD, Bh, Bl, DD, col0, DD, acc);
    int lane=tid&31, warp=tid>>5, wm=warp>>2, wn=warp&3;
    #pragma unroll
    for(int i=0;i<4;i++){
        int r0 = row0 + wm*64 + i*16 + (lane>>2);
        #pragma unroll
        for(int j=0;j<4;j++){
            int c = col0 + wn*32 + j*8 + (lane&3)*2;
            float b0=bias[c], b1=bias[c+1];
            out[(size_t)r0*N + c]       = acc[i][j][0] + b0;
            out[(size_t)r0*N + c+1]     = acc[i][j][1] + b1;
            out[(size_t)(r0+8)*N + c]   = acc[i][j][2] + b0;
            out[(size_t)(r0+8)*N + c+1] = acc[i][j][3] + b1;
        }
    }
}

// ---- O projection with residual ----
__global__ __launch_bounds__(256,1) void k_hmma_oproj(const __nv_bfloat16* __restrict__ Whi,
        const __nv_bfloat16* __restrict__ Wlo, const float* __restrict__ bias, float* __restrict__ x){
    extern __shared__ char sm[];
    int* rowidx = (int*)(sm + 2*HS_BUF);
    int tid=threadIdx.x;
    int row0=blockIdx.y*128, col0=blockIdx.x*128;
    if(tid<128) rowidx[tid]=row0+tid;
    __syncthreads();
    float acc[4][4][4];
    hmma_main(sm, rowidx, g_aohi, g_aolo, DD, Whi, Wlo, DD, col0, DD, acc);
    int lane=tid&31, warp=tid>>5, wm=warp>>2, wn=warp&3;
    #pragma unroll
    for(int i=0;i<4;i++){
        int r0 = row0 + wm*64 + i*16 + (lane>>2);
        #pragma unroll
        for(int j=0;j<4;j++){
            int c = col0 + wn*32 + j*8 + (lane&3)*2;
            float b0=bias[c], b1=bias[c+1];
            x[(size_t)r0*DD + c]       += acc[i][j][0] + b0;
            x[(size_t)r0*DD + c+1]     += acc[i][j][1] + b1;
            x[(size_t)(r0+8)*DD + c]   += acc[i][j][2] + b0;
            x[(size_t)(r0+8)*DD + c+1] += acc[i][j][3] + b1;
        }
    }
}

// ---- MoE2: 128x128, gathered h1 rows, gated atomic scatter ----
__global__ __launch_bounds__(256,1) void k_hmma_moe2(const __nv_bfloat16* __restrict__ Whi,
        const __nv_bfloat16* __restrict__ Wlo, const float* __restrict__ B2){
    int e=blockIdx.z, cnt=g_ecount[e], row0=blockIdx.x*128;
    if(row0>=cnt) return;
    extern __shared__ char sm[];
    int* rowidx = (int*)(sm + 2*HS_BUF);
    int tid=threadIdx.x;
    int col0=blockIdx.y*128;
    if(tid<128) rowidx[tid] = e*NTOK + row0 + tid;
    __syncthreads();
    float acc[4][4][4];
    hmma_main(sm, rowidx, g_h1hi, g_h1lo, FFD,
              Whi+(size_t)e*DD*FFD, Wlo+(size_t)e*DD*FFD, FFD, col0, FFD, acc);
    const float* bia = B2 + (size_t)e*DD;
    int lane=tid&31, warp=tid>>5, wm=warp>>2, wn=warp&3;
    #pragma unroll
    for(int i=0;i<4;i++){
        int r0 = row0 + wm*64 + i*16 + (lane>>2);
        #pragma unroll
        for(int j=0;j<4;j++){
            int c = col0 + wn*32 + j*8 + (lane&3)*2;
            float b0=bia[c], b1=bia[c+1];
            #pragma unroll
            for(int q=0;q<4;q++){
                int r = r0 + (q>=2?8:0);
                if(r>=cnt) continue;
                int tok=g_elist[e*NTOK+r];
                float gv=g_egate[e*NTOK+r];
                int cc = c + (q&1);
                atomicAdd(&g_moe[(size_t)tok*DD+cc], gv*(acc[i][j][q] + ((q&1)?b1:b0)));
            }
        }
    }
}

// ===== indexer scores (causal tile-skip) =====
__global__ __launch_bounds__(256) void k_idxscore(const float* __restrict__ hw){
    int kt=blockIdx.x, qt=blockIdx.y, b=blockIdx.z;
    int tx=threadIdx.x&15, ty=threadIdx.x>>4;
    if(kt>qt){
        #pragma unroll
        for(int i=0;i<4;i++){
            int q=qt*64+ty*4+i;
            float4 nv={NEGV,NEGV,NEGV,NEGV};
            *(float4*)&g_mask[((size_t)b*SSL+q)*SSL + kt*64+tx*4]=nv;
        }
        return;
    }
    __shared__ float Qs[64][68];
    __shared__ float Ks[64][68];
    float acc[4][4]={};
    for(int h=0;h<HHI;h++){
        for(int i=threadIdx.x;i<4096;i+=256){
            int r=i>>6, d=i&63;
            Qs[d][r]=g_qi[(size_t)(b*SSL+qt*64+r)*(HHI*DII)+h*64+d];
            Ks[d][r]=g_ki[(size_t)(b*SSL+kt*64+r)*(HHI*DII)+h*64+d];
        }
        __syncthreads();
        float w=hw[h];
        float dot[4][4]={};
        #pragma unroll 8
        for(int d=0;d<64;d++){
            float4 a4=*(const float4*)&Qs[d][ty*4];
            float4 b4=*(const float4*)&Ks[d][tx*4];
            float a[4]={a4.x,a4.y,a4.z,a4.w};
            float bb[4]={b4.x,b4.y,b4.z,b4.w};
            #pragma unroll
            for(int i=0;i<4;i++)
                #pragma unroll
                for(int j=0;j<4;j++) dot[i][j]+=a[i]*bb[j];
        }
        #pragma unroll
        for(int i=0;i<4;i++)
            #pragma unroll
            for(int j=0;j<4;j++) acc[i][j]+=fmaxf(dot[i][j],0.f)*w;
        __syncthreads();
    }
    #pragma unroll
    for(int i=0;i<4;i++){
        int q=qt*64+ty*4+i;
        #pragma unroll
        for(int j=0;j<4;j++){
            int k=kt*64+tx*4+j;
            g_mask[((size_t)b*SSL+q)*SSL+k]=acc[i][j]+((k<=q)?0.f:NEGV);
        }
    }
}

// ===== top-K =====
__global__ __launch_bounds__(512) void k_topk(){
    int q=blockIdx.x, b=blockIdx.y, t=threadIdx.x;
    size_t base=((size_t)b*SSL+q)*SSL;
    if(q < KTOP){
        for(int k=t;k<SSL;k+=512)
            g_mask[base+k]=(k<=q)?0.f:NEGV;
        return;
    }
    __shared__ float s[1024];
    s[t]=g_mask[base+t];
    s[t+512]=g_mask[base+t+512];
    __syncthreads();
    for(int size=2;size<=1024;size<<=1){
        for(int stride=size>>1;stride>0;stride>>=1){
            int lo=2*stride*(t/stride)+(t%stride);
            int hi=lo+stride;
            bool desc=((lo&size)==0);
            float a=s[lo], bv=s[hi];
            if((a<bv)==desc){ s[lo]=bv; s[hi]=a; }
            __syncthreads();
        }
    }
    float thr=s[KTOP-1];
    for(int k=t;k<SSL;k+=512){
        float v=g_mask[base+k];
        g_mask[base+k]=(k<=q && v>=thr)?0.f:NEGV;
    }
}

// ===== attention =====
__global__ __launch_bounds__(256) void k_attn(){
    int qt=blockIdx.x, h=blockIdx.y, b=blockIdx.z;
    int t=threadIdx.x, row=t>>4, cg=t&15;
    __shared__ float qs[16][68];
    __shared__ float Ks[64][68];
    __shared__ float Vs[64][68];
    __shared__ float Sc[16][68];
    __shared__ float mrow[16], lrow[16];
    int q0=qt*16;
    for(int i=t;i<16*64;i+=256){
        int r=i>>6, d=i&63;
        qs[r][d]=g_q[(size_t)(b*SSL+q0+r)*DD+h*64+d];
    }
    if(t<16){ mrow[t]=-1e30f; lrow[t]=0.f; }
    float oacc[4]={0.f,0.f,0.f,0.f};
    __syncthreads();
    const float* maskrow=g_mask+((size_t)b*SSL+(q0+row))*SSL;
    int kmax = q0 + 16;
    for(int k0=0;k0<kmax;k0+=64){
        for(int i=t;i<4096;i+=256){
            int r=i>>6, d=i&63;
            Ks[r][d]=g_k[(size_t)(b*SSL+k0+r)*DD+h*64+d];
            Vs[r][d]=g_v[(size_t)(b*SSL+k0+r)*DD+h*64+d];
        }
        __syncthreads();
        float sv[4]={0.f,0.f,0.f,0.f};
        #pragma unroll
        for(int d0=0;d0<64;d0+=4){
            float4 q4=*(const float4*)&qs[row][d0];
            #pragma unroll
            for(int j=0;j<4;j++){
                float4 k4=*(const float4*)&Ks[j*16+cg][d0];
                sv[j]+=q4.x*k4.x+q4.y*k4.y+q4.z*k4.z+q4.w*k4.w;
            }
        }
        #pragma unroll
        for(int j=0;j<4;j++) sv[j]=sv[j]*SCALE+maskrow[k0+j*16+cg];
        float mold=mrow[row], lold=lrow[row];
        float tmax=fmaxf(fmaxf(sv[0],sv[1]),fmaxf(sv[2],sv[3]));
        tmax=fmaxf(tmax,mold);
        #pragma unroll
        for(int off=8;off>0;off>>=1) tmax=fmaxf(tmax,__shfl_xor_sync(0xffffffffu,tmax,off,16));
        float c=__expf(mold-tmax);
        float lsum=0.f;
        #pragma unroll
        for(int j=0;j<4;j++){
            float p=__expf(sv[j]-tmax);
            Sc[row][j*16+cg]=p;
            lsum+=p;
        }
        #pragma unroll
        for(int off=8;off>0;off>>=1) lsum+=__shfl_xor_sync(0xffffffffu,lsum,off,16);
        if(cg==0){ mrow[row]=tmax; lrow[row]=lold*c+lsum; }
        __syncwarp();
        #pragma unroll
        for(int j=0;j<4;j++) oacc[j]*=c;
        #pragma unroll
        for(int k=0;k<64;k++){
            float s=Sc[row][k];
            float4 v4=*(const float4*)&Vs[k][cg*4];
            oacc[0]+=s*v4.x; oacc[1]+=s*v4.y; oacc[2]+=s*v4.z; oacc[3]+=s*v4.w;
        }
        __syncthreads();
    }
    float linv=1.0f/lrow[row];
    size_t ob = (size_t)(b*SSL+q0+row)*DD + h*64 + cg*4;
    #pragma unroll
    for(int j=0;j<4;j++){
        float v = oacc[j]*linv;
        __nv_bfloat16 hh=__float2bfloat16(v);
        g_aohi[ob+j]=hh;
        g_aolo[ob+j]=__float2bfloat16(v-__bfloat162float(hh));
    }
}

// ===== fused router =====
__global__ __launch_bounds__(256) void k_router(const float* __restrict__ rw, const float* __restrict__ rb){
    int n=blockIdx.x;
    int t=threadIdx.x, e=t>>5, lane=t&31;
    __shared__ float ms[DD];
    __shared__ float pe[EE];
    for(int i=t;i<DD;i+=256) ms[i]=g_m[(size_t)n*DD+i];
    g_moe[(size_t)n*DD+t]=0.f;
    g_moe[(size_t)n*DD+t+256]=0.f;
    __syncthreads();
    float s=0.f;
    for(int k=lane;k<DD;k+=32) s+=ms[k]*rw[k*EE+e];
    #pragma unroll
    for(int off=16;off>0;off>>=1) s+=__shfl_xor_sync(0xffffffffu,s,off);
    if(lane==0) pe[e]=s+rb[e];
    __syncthreads();
    if(t==0){
        float p[EE]; float mx=-1e30f;
        #pragma unroll
        for(int i=0;i<EE;i++){ p[i]=pe[i]; mx=fmaxf(mx,p[i]); }
        #pragma unroll
        for(int i=0;i<EE;i++) p[i]=__expf(p[i]-mx);
        int e1=0;
        for(int i=1;i<EE;i++) if(p[i]>p[e1]) e1=i;
        int e2=-1;
        for(int i=0;i<EE;i++) if(i!=e1 && (e2<0 || p[i]>p[e2])) e2=i;
        float den=p[e1]+p[e2];
        int pos=atomicAdd(&g_ecount[e1],1);
        g_elist[e1*NTOK+pos]=n; g_egate[e1*NTOK+pos]=p[e1]/den;
        pos=atomicAdd(&g_ecount[e2],1);
        g_elist[e2*NTOK+pos]=n; g_egate[e2*NTOK+pos]=p[e2]/den;
    }
}

// ===== host =====
extern "C" void kernel_launch(void* const* d_in, const int* in_sizes, int n_in,
                              void* d_out, int out_size){
    (void)in_sizes; (void)n_in; (void)out_size;
    const int*   ids  = (const int*)  d_in[0];
    const float* tok  = (const float*)d_in[1];
    const float* pos  = (const float*)d_in[2];
    const float* ln1g = (const float*)d_in[3];
    const float* ln1b = (const float*)d_in[4];
    const float* iqw  = (const float*)d_in[5];
    const float* iqb  = (const float*)d_in[6];
    const float* ikw  = (const float*)d_in[7];
    const float* ikb  = (const float*)d_in[8];
    const float* ihw  = (const float*)d_in[9];
    const float* wq   = (const float*)d_in[10];
    const float* bq   = (const float*)d_in[11];
    const float* wk   = (const float*)d_in[12];
    const float* bk   = (const float*)d_in[13];
    const float* wv   = (const float*)d_in[14];
    const float* bv   = (const float*)d_in[15];
    const float* wo   = (const float*)d_in[16];
    const float* bo   = (const float*)d_in[17];
    const float* ln2g = (const float*)d_in[18];
    const float* ln2b = (const float*)d_in[19];
    const float* rw   = (const float*)d_in[20];
    const float* rb   = (const float*)d_in[21];
    const float* ew1  = (const float*)d_in[22];
    const float* eb1  = (const float*)d_in[23];
    const float* ew2  = (const float*)d_in[24];
    const float* eb2  = (const float*)d_in[25];
    const float* lnfg = (const float*)d_in[26];
    const float* lnfb = (const float*)d_in[27];
    const float* ow   = (const float*)d_in[28];
    const float* ob   = (const float*)d_in[29];
    float* out = (float*)d_out;

    float *px,*ph,*pm,*pq,*pk,*pv,*pmoe,*pqi,*pki;
    int *pec;
    __nv_bfloat16 *phhi,*phlo,*pmhi,*pmlo,*powThi,*powTlo,*pw1Thi,*pw1Tlo,*pw2Thi,*pw2Tlo;
    __nv_bfloat16 *pwqh,*pwql,*pwkh,*pwkl,*pwvh,*pwvl,*pwoh,*pwol,*piqh,*piql,*pikh,*pikl;
    cudaGetSymbolAddress((void**)&px,g_x);
    cudaGetSymbolAddress((void**)&ph,g_h);
    cudaGetSymbolAddress((void**)&pm,g_m);
    cudaGetSymbolAddress((void**)&pq,g_q);
    cudaGetSymbolAddress((void**)&pk,g_k);
    cudaGetSymbolAddress((void**)&pv,g_v);
    cudaGetSymbolAddress((void**)&pmoe,g_moe);
    cudaGetSymbolAddress((void**)&pqi,g_qi);
    cudaGetSymbolAddress((void**)&pki,g_ki);
    cudaGetSymbolAddress((void**)&pec,g_ecount);
    cudaGetSymbolAddress((void**)&phhi,g_hhi);
    cudaGetSymbolAddress((void**)&phlo,g_hlo);
    cudaGetSymbolAddress((void**)&pmhi,g_mhi);
    cudaGetSymbolAddress((void**)&pmlo,g_mlo);
    cudaGetSymbolAddress((void**)&powThi,g_owThi);
    cudaGetSymbolAddress((void**)&powTlo,g_owTlo);
    cudaGetSymbolAddress((void**)&pw1Thi,g_w1Thi);
    cudaGetSymbolAddress((void**)&pw1Tlo,g_w1Tlo);
    cudaGetSymbolAddress((void**)&pw2Thi,g_w2Thi);
    cudaGetSymbolAddress((void**)&pw2Tlo,g_w2Tlo);
    cudaGetSymbolAddress((void**)&pwqh,g_wqThi);
    cudaGetSymbolAddress((void**)&pwql,g_wqTlo);
    cudaGetSymbolAddress((void**)&pwkh,g_wkThi);
    cudaGetSymbolAddress((void**)&pwkl,g_wkTlo);
    cudaGetSymbolAddress((void**)&pwvh,g_wvThi);
    cudaGetSymbolAddress((void**)&pwvl,g_wvTlo);
    cudaGetSymbolAddress((void**)&pwoh,g_woThi);
    cudaGetSymbolAddress((void**)&pwol,g_woTlo);
    cudaGetSymbolAddress((void**)&piqh,g_iqThi);
    cudaGetSymbolAddress((void**)&piql,g_iqTlo);
    cudaGetSymbolAddress((void**)&pikh,g_ikThi);
    cudaGetSymbolAddress((void**)&pikl,g_ikTlo);

    cudaFuncSetAttribute(k_hmma_vocab, cudaFuncAttributeMaxDynamicSharedMemorySize, M1_TOTAL);
    cudaFuncSetAttribute(k_hmma_moe1,  cudaFuncAttributeMaxDynamicSharedMemorySize, M1_TOTAL);
    cudaFuncSetAttribute(k_hmma_proj,  cudaFuncAttributeMaxDynamicSharedMemorySize, HS_TOTAL);
    cudaFuncSetAttribute(k_hmma_oproj, cudaFuncAttributeMaxDynamicSharedMemorySize, HS_TOTAL);
    cudaFuncSetAttribute(k_hmma_moe2,  cudaFuncAttributeMaxDynamicSharedMemorySize, HS_TOTAL);

    k_transcvtB<<<dim3(VV/32, DD/64, 1),256>>>(ow, powThi, powTlo, DD, VV);
    k_transcvtB<<<dim3(FFD/32, DD/64, LLN*EE),256>>>(ew1, pw1Thi, pw1Tlo, DD, FFD);
    k_transcvtB<<<dim3(DD/32, FFD/64, LLN*EE),256>>>(ew2, pw2Thi, pw2Tlo, FFD, DD);
    k_transcvtB<<<dim3(DD/32, DD/64, LLN),256>>>(wq, pwqh, pwql, DD, DD);
    k_transcvtB<<<dim3(DD/32, DD/64, LLN),256>>>(wk, pwkh, pwkl, DD, DD);
    k_transcvtB<<<dim3(DD/32, DD/64, LLN),256>>>(wv, pwvh, pwvl, DD, DD);
    k_transcvtB<<<dim3(DD/32, DD/64, LLN),256>>>(wo, pwoh, pwol, DD, DD);
    k_transcvtB<<<dim3((HHI*DII)/32, DD/64, LLN),256>>>(iqw, piqh, piql, DD, HHI*DII);
    k_transcvtB<<<dim3((HHI*DII)/32, DD/64, LLN),256>>>(ikw, pikh, pikl, DD, HHI*DII);

    k_embed<<<NTOK,512>>>(ids, tok, pos);

    for(int l=0;l<LLN;l++){
        k_ln<<<NTOK,256>>>(px, ln1g+l*DD, ln1b+l*DD, ph, phhi, phlo,
                           (l>0)?pmoe:nullptr, nullptr);
        {   H3 p;
            p.h0=piqh+(size_t)l*HHI*DII*DD; p.l0=piql+(size_t)l*HHI*DII*DD; p.c0=iqb+l*HHI*DII; p.o0=pqi;
            p.h1=pikh+(size_t)l*HHI*DII*DD; p.l1=pikl+(size_t)l*HHI*DII*DD; p.c1=ikb+l*HHI*DII; p.o1=pki;
            p.h2=p.h0; p.l2=p.l0; p.c2=p.c0; p.o2=pqi;
            k_hmma_proj<<<dim3((HHI*DII)/128, NTOK/128, 2),256,HS_TOTAL>>>(p, HHI*DII);
        }
        k_idxscore<<<dim3(SSL/64,SSL/64,BB),256>>>(ihw+l*HHI);
        k_topk<<<dim3(SSL,BB),512>>>();
        {   H3 p;
            p.h0=pwqh+(size_t)l*DD*DD; p.l0=pwql+(size_t)l*DD*DD; p.c0=bq+l*DD; p.o0=pq;
            p.h1=pwkh+(size_t)l*DD*DD; p.l1=pwkl+(size_t)l*DD*DD; p.c1=bk+l*DD; p.o1=pk;
            p.h2=pwvh+(size_t)l*DD*DD; p.l2=pwvl+(size_t)l*DD*DD; p.c2=bv+l*DD; p.o2=pv;
            k_hmma_proj<<<dim3(DD/128, NTOK/128, 3),256,HS_TOTAL>>>(p, DD);
        }
        k_attn<<<dim3(SSL/16,HHN,BB),256>>>();
        k_hmma_oproj<<<dim3(DD/128, NTOK/128),256,HS_TOTAL>>>(
            pwoh+(size_t)l*DD*DD, pwol+(size_t)l*DD*DD, bo+l*DD, px);

        k_ln<<<NTOK,256>>>(px, ln2g+l*DD, ln2b+l*DD, pm, pmhi, pmlo, nullptr, pec);
        k_router<<<NTOK,256>>>(rw+(size_t)l*DD*EE, rb+l*EE);
        k_hmma_moe1<<<dim3(NTOK/128, FFD/256, EE),256,M1_TOTAL>>>(
            pw1Thi+(size_t)l*EE*FFD*DD, pw1Tlo+(size_t)l*EE*FFD*DD, eb1+(size_t)l*EE*FFD);
        k_hmma_moe2<<<dim3(NTOK/128, DD/128, EE),256,HS_TOTAL>>>(
            pw2Thi+(size_t)l*EE*DD*FFD, pw2Tlo+(size_t)l*EE*DD*FFD, eb2+(size_t)l*EE*DD);
    }

    k_ln<<<NTOK,256>>>(px, lnfg, lnfb, ph, phhi, phlo, pmoe, nullptr);
    k_hmma_vocab<<<dim3(NTOK/128, VV/256),256,M1_TOTAL>>>(ob, out);
}

// round 14
// speedup vs baseline: 1.0087x; 1.0087x over previous
#include <cuda_runtime.h>
#include <cuda_bf16.h>
#include <math.h>
#include <stdint.h>

#define BB 2
#define SSL 1024
#define NTOK 2048
#define DD 512
#define HHN 8
#define HHI 4
#define DII 64
#define FFD 2048
#define EE 8
#define VV 32000
#define KTOP 256
#define NEGV (-1e9f)
#define EPSV 1e-5f
#define LLN 2
#define SCALE 0.125f

__device__ float g_x[NTOK*DD];
__device__ float g_h[NTOK*DD];
__device__ float g_m[NTOK*DD];
__device__ float g_q[NTOK*DD];
__device__ float g_k[NTOK*DD];
__device__ float g_v[NTOK*DD];
__device__ float g_moe[NTOK*DD];
__device__ float g_mask[(size_t)BB*SSL*SSL];
__device__ int g_ecount[EE];
__device__ int g_elist[EE*NTOK];
__device__ float g_egate[EE*NTOK];
__device__ alignas(16) __nv_bfloat16 g_hhi[NTOK*DD];
__device__ alignas(16) __nv_bfloat16 g_hlo[NTOK*DD];
__device__ alignas(16) __nv_bfloat16 g_mhi[NTOK*DD];
__device__ alignas(16) __nv_bfloat16 g_mlo[NTOK*DD];
__device__ alignas(16) __nv_bfloat16 g_aohi[NTOK*DD];
__device__ alignas(16) __nv_bfloat16 g_aolo[NTOK*DD];
__device__ alignas(16) float g_qi[NTOK*HHI*DII];
__device__ alignas(16) float g_ki[NTOK*HHI*DII];
__device__ alignas(16) __nv_bfloat16 g_owThi[(size_t)VV*DD];
__device__ alignas(16) __nv_bfloat16 g_owTlo[(size_t)VV*DD];
__device__ alignas(16) __nv_bfloat16 g_w1Thi[(size_t)LLN*EE*FFD*DD];
__device__ alignas(16) __nv_bfloat16 g_w1Tlo[(size_t)LLN*EE*FFD*DD];
__device__ alignas(16) __nv_bfloat16 g_w2Thi[(size_t)LLN*EE*DD*FFD];
__device__ alignas(16) __nv_bfloat16 g_w2Tlo[(size_t)LLN*EE*DD*FFD];
__device__ alignas(16) __nv_bfloat16 g_h1hi[(size_t)EE*NTOK*FFD];
__device__ alignas(16) __nv_bfloat16 g_h1lo[(size_t)EE*NTOK*FFD];
__device__ alignas(16) __nv_bfloat16 g_wqThi[LLN*DD*DD];
__device__ alignas(16) __nv_bfloat16 g_wqTlo[LLN*DD*DD];
__device__ alignas(16) __nv_bfloat16 g_wkThi[LLN*DD*DD];
__device__ alignas(16) __nv_bfloat16 g_wkTlo[LLN*DD*DD];
__device__ alignas(16) __nv_bfloat16 g_wvThi[LLN*DD*DD];
__device__ alignas(16) __nv_bfloat16 g_wvTlo[LLN*DD*DD];
__device__ alignas(16) __nv_bfloat16 g_woThi[LLN*DD*DD];
__device__ alignas(16) __nv_bfloat16 g_woTlo[LLN*DD*DD];
__device__ alignas(16) __nv_bfloat16 g_iqThi[LLN*HHI*DII*DD];
__device__ alignas(16) __nv_bfloat16 g_iqTlo[LLN*HHI*DII*DD];
__device__ alignas(16) __nv_bfloat16 g_ikThi[LLN*HHI*DII*DD];
__device__ alignas(16) __nv_bfloat16 g_ikTlo[LLN*HHI*DII*DD];

__device__ __forceinline__ float gelu_tanh(float x){
    float x3 = x*x*x;
    return 0.5f*x*(1.f + tanhf(0.7978845608028654f*(x + 0.044715f*x3)));
}

__global__ void k_embed(const int* __restrict__ ids, const float* __restrict__ tok, const float* __restrict__ pos){
    int n=blockIdx.x, t=threadIdx.x;
    g_x[(size_t)n*DD+t] = tok[(size_t)ids[n]*DD+t] + pos[(size_t)(n%SSL)*DD+t];
}

__global__ __launch_bounds__(256) void k_ln(float* __restrict__ in, const float* __restrict__ g,
        const float* __restrict__ b, float* __restrict__ out,
        __nv_bfloat16* __restrict__ hi, __nv_bfloat16* __restrict__ lo,
        const float* __restrict__ radd, int* __restrict__ ecz){
    int r=blockIdx.x, t=threadIdx.x;
    int lane=t&31, wid=t>>5;
    __shared__ float red1[8], red2[8];
    if(ecz && r==0 && t<EE) ecz[t]=0;
    float v0=in[(size_t)r*DD+t], v1=in[(size_t)r*DD+t+256];
    if(radd){
        v0 += radd[(size_t)r*DD+t];
        v1 += radd[(size_t)r*DD+t+256];
        in[(size_t)r*DD+t]=v0;
        in[(size_t)r*DD+t+256]=v1;
    }
    float s=v0+v1;
    #pragma unroll
    for(int off=16;off>0;off>>=1) s+=__shfl_xor_sync(0xffffffffu,s,off);
    if(lane==0) red1[wid]=s;
    __syncthreads();
    float mu=(red1[0]+red1[1]+red1[2]+red1[3]+red1[4]+red1[5]+red1[6]+red1[7])*(1.0f/DD);
    float d0=v0-mu, d1=v1-mu;
    float s2=d0*d0+d1*d1;
    #pragma unroll
    for(int off=16;off>0;off>>=1) s2+=__shfl_xor_sync(0xffffffffu,s2,off);
    if(lane==0) red2[wid]=s2;
    __syncthreads();
    float var=(red2[0]+red2[1]+red2[2]+red2[3]+red2[4]+red2[5]+red2[6]+red2[7])*(1.0f/DD);
    float rs=rsqrtf(var+EPSV);
    float o0=d0*rs*g[t]+b[t];
    float o1=d1*rs*g[t+256]+b[t+256];
    out[(size_t)r*DD+t]=o0;
    out[(size_t)r*DD+t+256]=o1;
    if(hi){
        __nv_bfloat16 h0=__float2bfloat16(o0), h1=__float2bfloat16(o1);
        hi[(size_t)r*DD+t]=h0;
        hi[(size_t)r*DD+t+256]=h1;
        lo[(size_t)r*DD+t]=__float2bfloat16(o0-__bfloat162float(h0));
        lo[(size_t)r*DD+t+256]=__float2bfloat16(o1-__bfloat162float(h1));
    }
}

__global__ __launch_bounds__(256) void k_transcvtB(const float* __restrict__ W,
        __nv_bfloat16* __restrict__ Thi, __nv_bfloat16* __restrict__ Tlo, int K, int N){
    int z=blockIdx.z;
    W   += (size_t)z*K*N;
    Thi += (size_t)z*N*K;
    Tlo += (size_t)z*N*K;
    __shared__ float t[32][66];
    int n0=blockIdx.x*32, k0=blockIdx.y*64;
    int lane=threadIdx.x&31, wid=threadIdx.x>>5;
    #pragma unroll
    for(int i=0;i<8;i++){
        int kk=wid*8+i;
        t[lane][kk]=W[(size_t)(k0+kk)*N + n0+lane];
    }
    __syncthreads();
    #pragma unroll
    for(int j=0;j<4;j++){
        int n=wid*4+j;
        float2 ab=*(float2*)&t[n][2*lane];
        __nv_bfloat16 ha=__float2bfloat16(ab.x), hb=__float2bfloat16(ab.y);
        uint32_t hw=(uint32_t)__bfloat16_as_ushort(ha) | ((uint32_t)__bfloat16_as_ushort(hb)<<16);
        __nv_bfloat16 la=__float2bfloat16(ab.x-__bfloat162float(ha));
        __nv_bfloat16 lb=__float2bfloat16(ab.y-__bfloat162float(hb));
        uint32_t lw=(uint32_t)__bfloat16_as_ushort(la) | ((uint32_t)__bfloat16_as_ushort(lb)<<16);
        *(uint32_t*)(Thi + (size_t)(n0+n)*K + k0 + 2*lane)=hw;
        *(uint32_t*)(Tlo + (size_t)(n0+n)*K + k0 + 2*lane)=lw;
    }
}

// ================= HMMA primitives =================
__device__ __forceinline__ uint32_t smem_u32(const void* p){
    uint32_t a;
    asm("{ .reg .u64 t; cvta.to.shared.u64 t, %1; cvt.u32.u64 %0, t; }" : "=r"(a) : "l"(p));
    return a;
}
__device__ __forceinline__ void ldsm4(uint32_t (&r)[4], uint32_t a){
    asm volatile("ldmatrix.sync.aligned.m8n8.x4.shared.b16 {%0,%1,%2,%3}, [%4];"
        : "=r"(r[0]),"=r"(r[1]),"=r"(r[2]),"=r"(r[3]) : "r"(a));
}
__device__ __forceinline__ void ldsm2(uint32_t (&r)[2], uint32_t a){
    asm volatile("ldmatrix.sync.aligned.m8n8.x2.shared.b16 {%0,%1}, [%2];"
        : "=r"(r[0]),"=r"(r[1]) : "r"(a));
}
__device__ __forceinline__ void mma16816(float (&c)[4], const uint32_t (&a)[4], const uint32_t (&b)[2]){
    asm volatile("mma.sync.aligned.m16n8k16.row.col.f32.bf16.bf16.f32 "
        "{%0,%1,%2,%3}, {%4,%5,%6,%7}, {%8,%9}, {%0,%1,%2,%3};"
        : "+f"(c[0]),"+f"(c[1]),"+f"(c[2]),"+f"(c[3])
        : "r"(a[0]),"r"(a[1]),"r"(a[2]),"r"(a[3]), "r"(b[0]),"r"(b[1]));
}
__device__ __forceinline__ void cpasync16(uint32_t dst, const void* src){
    asm volatile("{ .reg .u64 g; cvta.to.global.u64 g, %1; cp.async.ca.shared.global [%0], [g], 16; }"
        :: "r"(dst), "l"(src));
}
#define HS_BUF 24576
#define HS_TILE 6144
#define HS_TOTAL 49664

// register-staged double-buffered 128x128 mainloop (R12-proven)
__device__ __forceinline__ void hmma_main(char* sm, const int* rowidx,
    const __nv_bfloat16* __restrict__ Ahi, const __nv_bfloat16* __restrict__ Alo, int sA,
    const __nv_bfloat16* __restrict__ Bhi, const __nv_bfloat16* __restrict__ Blo, int sB,
    int col0, int K, float (&acc)[4][4][4])
{
    int tid=threadIdx.x, lane=tid&31, warp=tid>>5;
    int wm=warp>>2, wn=warp&3;
    uint32_t smb = smem_u32(sm);
    #pragma unroll
    for(int i=0;i<4;i++)
        #pragma unroll
        for(int j=0;j<4;j++)
            #pragma unroll
            for(int q=0;q<4;q++) acc[i][j][q]=0.f;

    int ltile[4], lrow[4], lhalf[4];
    #pragma unroll
    for(int t=0;t<4;t++){
        int i = tid + t*256;
        ltile[t]=i>>8; lrow[t]=(i&255)>>1; lhalf[t]=(i&1)*8;
    }
    uint4 pre[4];
    const int NS = K>>4;
    int lb = lane&15;
    uint32_t boff = (uint32_t)((wn*32 + (lb&7))*48 + ((lb&8)?16:0));
    uint32_t aoff = (uint32_t)((wm*64 + (lane&7) + ((lane&8)?8:0))*48 + ((lane&16)?16:0));

    auto ldg = [&](int s){
        int k0 = s<<4;
        #pragma unroll
        for(int t=0;t<4;t++){
            const __nv_bfloat16* src;
            int row=lrow[t];
            if(ltile[t]==0)      src = Ahi + (size_t)rowidx[row]*sA;
            else if(ltile[t]==1) src = Alo + (size_t)rowidx[row]*sA;
            else if(ltile[t]==2) src = Bhi + (size_t)(col0+row)*sB;
            else                 src = Blo + (size_t)(col0+row)*sB;
            pre[t] = *(const uint4*)(src + k0 + lhalf[t]);
        }
    };
    auto sts = [&](int b){
        #pragma unroll
        for(int t=0;t<4;t++)
            *(uint4*)(sm + b*HS_BUF + ltile[t]*HS_TILE + lrow[t]*48 + lhalf[t]*2) = pre[t];
    };
    ldg(0); sts(0);
    __syncthreads();
    for(int s=0;s<NS;s++){
        int b=s&1;
        if(s+1<NS) ldg(s+1);
        uint32_t base = smb + b*HS_BUF;
        uint32_t bh[4][2], bl[4][2];
        #pragma unroll
        for(int j=0;j<4;j++){
            ldsm2(bh[j], base + 2*HS_TILE + boff + j*8*48);
            ldsm2(bl[j], base + 3*HS_TILE + boff + j*8*48);
        }
        #pragma unroll
        for(int i=0;i<4;i++){
            uint32_t a[4];
            ldsm4(a, base + aoff + i*16*48);
            #pragma unroll
            for(int j=0;j<4;j++){ mma16816(acc[i][j], a, bh[j]); mma16816(acc[i][j], a, bl[j]); }
            ldsm4(a, base + HS_TILE + aoff + i*16*48);
            #pragma unroll
            for(int j=0;j<4;j++) mma16816(acc[i][j], a, bh[j]);
        }
        if(s+1<NS) sts(b^1);
        __syncthreads();
    }
}

// ---- vocab: 128x256 tile, cp.async pipeline; grid (NTOK/128, VV/256) ----
#define V_BUF 36864
#define V_TOTAL 73728
__global__ __launch_bounds__(256,1) void k_hmma_vocab(const float* __restrict__ ob, float* __restrict__ out){
    extern __shared__ char sm[];
    int tid=threadIdx.x, lane=tid&31, warp=tid>>5;
    int wm=warp>>2, wn=warp&3;
    int row0=blockIdx.x*128, col0=blockIdx.y*256;
    uint32_t smb = smem_u32(sm);
    float acc[4][8][4];
    #pragma unroll
    for(int i=0;i<4;i++)
        #pragma unroll
        for(int j=0;j<8;j++)
            #pragma unroll
            for(int q=0;q<4;q++) acc[i][j][q]=0.f;

    auto load_stage = [&](int s, int b){
        int k0 = s<<4;
        #pragma unroll
        for(int c=0;c<6;c++){
            int i = tid + c*256;
            const __nv_bfloat16* src; uint32_t dst;
            if(i<512){
                int tile=i>>8, rem=i&255, row=rem>>1, half=(rem&1)*8;
                src = (tile? g_hlo : g_hhi) + (size_t)(row0+row)*DD + k0 + half;
                dst = smb + b*V_BUF + tile*6144 + row*48 + half*2;
            }else{
                int ii=i-512, tile=ii>>9, rem=ii&511, row=rem>>1, half=(rem&1)*8;
                src = (tile? g_owTlo : g_owThi) + (size_t)(col0+row)*DD + k0 + half;
                dst = smb + b*V_BUF + 12288 + tile*12288 + row*48 + half*2;
            }
            cpasync16(dst, src);
        }
        asm volatile("cp.async.commit_group;" ::: "memory");
    };
    load_stage(0,0);
    asm volatile("cp.async.wait_group 0;" ::: "memory");
    __syncthreads();

    int lb = lane&15;
    uint32_t boff = (uint32_t)((wn*64 + (lb&7))*48 + ((lb&8)?16:0));
    uint32_t aoff = (uint32_t)((wm*64 + (lane&7) + ((lane&8)?8:0))*48 + ((lane&16)?16:0));
    const int NS = DD>>4;
    for(int s=0;s<NS;s++){
        int b=s&1;
        if(s+1<NS) load_stage(s+1, b^1);
        uint32_t base = smb + b*V_BUF;
        uint32_t bh[8][2], bl[8][2];
        #pragma unroll
        for(int j=0;j<8;j++){
            ldsm2(bh[j], base + 12288 + boff + j*8*48);
            ldsm2(bl[j], base + 24576 + boff + j*8*48);
        }
        #pragma unroll
        for(int i=0;i<4;i++){
            uint32_t a[4];
            ldsm4(a, base + aoff + i*16*48);
            #pragma unroll
            for(int j=0;j<8;j++){ mma16816(acc[i][j], a, bh[j]); mma16816(acc[i][j], a, bl[j]); }
            ldsm4(a, base + 6144 + aoff + i*16*48);
            #pragma unroll
            for(int j=0;j<8;j++) mma16816(acc[i][j], a, bh[j]);
        }
        if(s+1<NS) asm volatile("cp.async.wait_group 0;" ::: "memory");
        __syncthreads();
    }
    #pragma unroll
    for(int i=0;i<4;i++){
        int r0 = row0 + wm*64 + i*16 + (lane>>2);
        #pragma unroll
        for(int j=0;j<8;j++){
            int c = col0 + wn*64 + j*8 + (lane&3)*2;
            float b0=ob[c], b1=ob[c+1];
            out[(size_t)r0*VV + c]       = acc[i][j][0] + b0;
            out[(size_t)r0*VV + c+1]     = acc[i][j][1] + b1;
            out[(size_t)(r0+8)*VV + c]   = acc[i][j][2] + b0;
            out[(size_t)(r0+8)*VV + c+1] = acc[i][j][3] + b1;
        }
    }
}

// ---- generic projection: fp32 out, 3-way batched ----
struct H3 {
    const __nv_bfloat16 *h0,*l0,*h1,*l1,*h2,*l2;
    const float *c0,*c1,*c2;
    float *o0,*o1,*o2;
};
__global__ __launch_bounds__(256,1) void k_hmma_proj(H3 p, int N){
    extern __shared__ char sm[];
    int* rowidx = (int*)(sm + 2*HS_BUF);
    int tid=threadIdx.x;
    int row0=blockIdx.y*128, col0=blockIdx.x*128;
    const __nv_bfloat16 *Bh,*Bl; const float* bias; float* out;
    if(blockIdx.z==0){Bh=p.h0;Bl=p.l0;bias=p.c0;out=p.o0;}
    else if(blockIdx.z==1){Bh=p.h1;Bl=p.l1;bias=p.c1;out=p.o1;}
    else {Bh=p.h2;Bl=p.l2;bias=p.c2;out=p.o2;}
    if(tid<128) rowidx[tid]=row0+tid;
    __syncthreads();
    float acc[4][4][4];
    hmma_main(sm, rowidx, g_hhi, g_hlo, DD, Bh, Bl, DD, col0, DD, acc);
    int lane=tid&31, warp=tid>>5, wm=warp>>2, wn=warp&3;
    #pragma unroll
    for(int i=0;i<4;i++){
        int r0 = row0 + wm*64 + i*16 + (lane>>2);
        #pragma unroll
        for(int j=0;j<4;j++){
            int c = col0 + wn*32 + j*8 + (lane&3)*2;
            float b0=bias[c], b1=bias[c+1];
            out[(size_t)r0*N + c]       = acc[i][j][0] + b0;
            out[(size_t)r0*N + c+1]     = acc[i][j][1] + b1;
            out[(size_t)(r0+8)*N + c]   = acc[i][j][2] + b0;
            out[(size_t)(r0+8)*N + c+1] = acc[i][j][3] + b1;
        }
    }
}

// ---- O projection with residual ----
__global__ __launch_bounds__(256,1) void k_hmma_oproj(const __nv_bfloat16* __restrict__ Whi,
        const __nv_bfloat16* __restrict__ Wlo, const float* __restrict__ bias, float* __restrict__ x){
    extern __shared__ char sm[];
    int* rowidx = (int*)(sm + 2*HS_BUF);
    int tid=threadIdx.x;
    int row0=blockIdx.y*128, col0=blockIdx.x*128;
    if(tid<128) rowidx[tid]=row0+tid;
    __syncthreads();
    float acc[4][4][4];
    hmma_main(sm, rowidx, g_aohi, g_aolo, DD, Whi, Wlo, DD, col0, DD, acc);
    int lane=tid&31, warp=tid>>5, wm=warp>>2, wn=warp&3;
    #pragma unroll
    for(int i=0;i<4;i++){
        int r0 = row0 + wm*64 + i*16 + (lane>>2);
        #pragma unroll
        for(int j=0;j<4;j++){
            int c = col0 + wn*32 + j*8 + (lane&3)*2;
            float b0=bias[c], b1=bias[c+1];
            x[(size_t)r0*DD + c]       += acc[i][j][0] + b0;
            x[(size_t)r0*DD + c+1]     += acc[i][j][1] + b1;
            x[(size_t)(r0+8)*DD + c]   += acc[i][j][2] + b0;
            x[(size_t)(r0+8)*DD + c+1] += acc[i][j][3] + b1;
        }
    }
}

// ---- MoE1: 128x128, gathered rows, GELU + split-bf16 out; grid (NTOK/128, FFD/128, EE) ----
__global__ __launch_bounds__(256,1) void k_hmma_moe1(const __nv_bfloat16* __restrict__ Whi,
        const __nv_bfloat16* __restrict__ Wlo, const float* __restrict__ B1){
    int e=blockIdx.z, cnt=g_ecount[e], row0=blockIdx.x*128;
    if(row0>=cnt) return;
    extern __shared__ char sm[];
    int* rowidx = (int*)(sm + 2*HS_BUF);
    int tid=threadIdx.x;
    int col0=blockIdx.y*128;
    if(tid<128){
        int r=row0+tid;
        rowidx[tid] = (r<cnt)? g_elist[e*NTOK+r] : g_elist[e*NTOK];
    }
    __syncthreads();
    float acc[4][4][4];
    hmma_main(sm, rowidx, g_mhi, g_mlo, DD,
              Whi+(size_t)e*FFD*DD, Wlo+(size_t)e*FFD*DD, DD, col0, DD, acc);
    const float* bia = B1 + (size_t)e*FFD;
    int lane=tid&31, warp=tid>>5, wm=warp>>2, wn=warp&3;
    #pragma unroll
    for(int i=0;i<4;i++){
        int r0 = row0 + wm*64 + i*16 + (lane>>2);
        #pragma unroll
        for(int j=0;j<4;j++){
            int c = col0 + wn*32 + j*8 + (lane&3)*2;
            float b0=bia[c], b1=bia[c+1];
            #pragma unroll
            for(int q=0;q<4;q++){
                int r = r0 + (q>=2?8:0);
                if(r>=cnt) continue;
                int cc = c + (q&1);
                float v = gelu_tanh(acc[i][j][q] + ((q&1)?b1:b0));
                __nv_bfloat16 h=__float2bfloat16(v);
                size_t o = ((size_t)e*NTOK + r)*FFD + cc;
                g_h1hi[o]=h; g_h1lo[o]=__float2bfloat16(v-__bfloat162float(h));
            }
        }
    }
}

// ---- MoE2: 128x128, gated atomic scatter ----
__global__ __launch_bounds__(256,1) void k_hmma_moe2(const __nv_bfloat16* __restrict__ Whi,
        const __nv_bfloat16* __restrict__ Wlo, const float* __restrict__ B2){
    int e=blockIdx.z, cnt=g_ecount[e], row0=blockIdx.x*128;
    if(row0>=cnt) return;
    extern __shared__ char sm[];
    int* rowidx = (int*)(sm + 2*HS_BUF);
    int tid=threadIdx.x;
    int col0=blockIdx.y*128;
    if(tid<128) rowidx[tid] = e*NTOK + row0 + tid;
    __syncthreads();
    float acc[4][4][4];
    hmma_main(sm, rowidx, g_h1hi, g_h1lo, FFD,
              Whi+(size_t)e*DD*FFD, Wlo+(size_t)e*DD*FFD, FFD, col0, FFD, acc);
    const float* bia = B2 + (size_t)e*DD;
    int lane=tid&31, warp=tid>>5, wm=warp>>2, wn=warp&3;
    #pragma unroll
    for(int i=0;i<4;i++){
        int r0 = row0 + wm*64 + i*16 + (lane>>2);
        #pragma unroll
        for(int j=0;j<4;j++){
            int c = col0 + wn*32 + j*8 + (lane&3)*2;
            float b0=bia[c], b1=bia[c+1];
            #pragma unroll
            for(int q=0;q<4;q++){
                int r = r0 + (q>=2?8:0);
                if(r>=cnt) continue;
                int tok=g_elist[e*NTOK+r];
                float gv=g_egate[e*NTOK+r];
                int cc = c + (q&1);
                atomicAdd(&g_moe[(size_t)tok*DD+cc], gv*(acc[i][j][q] + ((q&1)?b1:b0)));
            }
        }
    }
}

// ===== indexer scores (causal tile-skip) =====
__global__ __launch_bounds__(256) void k_idxscore(const float* __restrict__ hw){
    int kt=blockIdx.x, qt=blockIdx.y, b=blockIdx.z;
    int tx=threadIdx.x&15, ty=threadIdx.x>>4;
    if(kt>qt){
        #pragma unroll
        for(int i=0;i<4;i++){
            int q=qt*64+ty*4+i;
            float4 nv={NEGV,NEGV,NEGV,NEGV};
            *(float4*)&g_mask[((size_t)b*SSL+q)*SSL + kt*64+tx*4]=nv;
        }
        return;
    }
    __shared__ float Qs[64][68];
    __shared__ float Ks[64][68];
    float acc[4][4]={};
    for(int h=0;h<HHI;h++){
        for(int i=threadIdx.x;i<4096;i+=256){
            int r=i>>6, d=i&63;
            Qs[d][r]=g_qi[(size_t)(b*SSL+qt*64+r)*(HHI*DII)+h*64+d];
            Ks[d][r]=g_ki[(size_t)(b*SSL+kt*64+r)*(HHI*DII)+h*64+d];
        }
        __syncthreads();
        float w=hw[h];
        float dot[4][4]={};
        #pragma unroll 8
        for(int d=0;d<64;d++){
            float4 a4=*(const float4*)&Qs[d][ty*4];
            float4 b4=*(const float4*)&Ks[d][tx*4];
            float a[4]={a4.x,a4.y,a4.z,a4.w};
            float bb[4]={b4.x,b4.y,b4.z,b4.w};
            #pragma unroll
            for(int i=0;i<4;i++)
                #pragma unroll
                for(int j=0;j<4;j++) dot[i][j]+=a[i]*bb[j];
        }
        #pragma unroll
        for(int i=0;i<4;i++)
            #pragma unroll
            for(int j=0;j<4;j++) acc[i][j]+=fmaxf(dot[i][j],0.f)*w;
        __syncthreads();
    }
    #pragma unroll
    for(int i=0;i<4;i++){
        int q=qt*64+ty*4+i;
        #pragma unroll
        for(int j=0;j<4;j++){
            int k=kt*64+tx*4+j;
            g_mask[((size_t)b*SSL+q)*SSL+k]=acc[i][j]+((k<=q)?0.f:NEGV);
        }
    }
}

// ===== top-K =====
__global__ __launch_bounds__(512) void k_topk(){
    int q=blockIdx.x, b=blockIdx.y, t=threadIdx.x;
    size_t base=((size_t)b*SSL+q)*SSL;
    if(q < KTOP){
        for(int k=t;k<SSL;k+=512)
            g_mask[base+k]=(k<=q)?0.f:NEGV;
        return;
    }
    __shared__ float s[1024];
    s[t]=g_mask[base+t];
    s[t+512]=g_mask[base+t+512];
    __syncthreads();
    for(int size=2;size<=1024;size<<=1){
        for(int stride=size>>1;stride>0;stride>>=1){
            int lo=2*stride*(t/stride)+(t%stride);
            int hi=lo+stride;
            bool desc=((lo&size)==0);
            float a=s[lo], bv=s[hi];
            if((a<bv)==desc){ s[lo]=bv; s[hi]=a; }
            __syncthreads();
        }
    }
    float thr=s[KTOP-1];
    for(int k=t;k<SSL;k+=512){
        float v=g_mask[base+k];
        g_mask[base+k]=(k<=q && v>=thr)?0.f:NEGV;
    }
}

// ===== attention: float4 tile loads, conflict-free compute, causal skip =====
__global__ __launch_bounds__(256) void k_attn(){
    int qt=blockIdx.x, h=blockIdx.y, b=blockIdx.z;
    int t=threadIdx.x, row=t>>4, cg=t&15;
    __shared__ float qs[16][68];
    __shared__ float Ks[64][68];
    __shared__ float Vs[64][68];
    __shared__ float Sc[16][68];
    __shared__ float mrow[16], lrow[16];
    int q0=qt*16;
    {   // q tile: 16x64 floats = 256 float4
        int r=t>>4, d4=(t&15)*4;
        *(float4*)&qs[r][d4] = *(const float4*)&g_q[(size_t)(b*SSL+q0+r)*DD+h*64+d4];
    }
    if(t<16){ mrow[t]=-1e30f; lrow[t]=0.f; }
    float oacc[4]={0.f,0.f,0.f,0.f};
    __syncthreads();
    const float* maskrow=g_mask+((size_t)b*SSL+(q0+row))*SSL;
    int kmax = q0 + 16;
    for(int k0=0;k0<kmax;k0+=64){
        // K/V tiles: 64x64 floats = 1024 float4 each; 256 threads x 4 iters
        #pragma unroll
        for(int c=0;c<4;c++){
            int i = t + c*256;
            int r=i>>4, d4=(i&15)*4;
            *(float4*)&Ks[r][d4] = *(const float4*)&g_k[(size_t)(b*SSL+k0+r)*DD+h*64+d4];
            *(float4*)&Vs[r][d4] = *(const float4*)&g_v[(size_t)(b*SSL+k0+r)*DD+h*64+d4];
        }
        __syncthreads();
        float sv[4]={0.f,0.f,0.f,0.f};
        #pragma unroll
        for(int d0=0;d0<64;d0+=4){
            float4 q4=*(const float4*)&qs[row][d0];
            #pragma unroll
            for(int j=0;j<4;j++){
                float4 k4=*(const float4*)&Ks[j*16+cg][d0];
                sv[j]+=q4.x*k4.x+q4.y*k4.y+q4.z*k4.z+q4.w*k4.w;
            }
        }
        #pragma unroll
        for(int j=0;j<4;j++) sv[j]=sv[j]*SCALE+maskrow[k0+j*16+cg];
        float mold=mrow[row], lold=lrow[row];
        float tmax=fmaxf(fmaxf(sv[0],sv[1]),fmaxf(sv[2],sv[3]));
        tmax=fmaxf(tmax,mold);
        #pragma unroll
        for(int off=8;off>0;off>>=1) tmax=fmaxf(tmax,__shfl_xor_sync(0xffffffffu,tmax,off,16));
        float c=__expf(mold-tmax);
        float lsum=0.f;
        #pragma unroll
        for(int j=0;j<4;j++){
            float p=__expf(sv[j]-tmax);
            Sc[row][j*16+cg]=p;
            lsum+=p;
        }
        #pragma unroll
        for(int off=8;off>0;off>>=1) lsum+=__shfl_xor_sync(0xffffffffu,lsum,off,16);
        if(cg==0){ mrow[row]=tmax; lrow[row]=lold*c+lsum; }
        __syncwarp();
        #pragma unroll
        for(int j=0;j<4;j++) oacc[j]*=c;
        #pragma unroll
        for(int k=0;k<64;k++){
            float s=Sc[row][k];
            float4 v4=*(const float4*)&Vs[k][cg*4];
            oacc[0]+=s*v4.x; oacc[1]+=s*v4.y; oacc[2]+=s*v4.z; oacc[3]+=s*v4.w;
        }
        __syncthreads();
    }
    float linv=1.0f/lrow[row];
    size_t ob = (size_t)(b*SSL+q0+row)*DD + h*64 + cg*4;
    #pragma unroll
    for(int j=0;j<4;j++){
        float v = oacc[j]*linv;
        __nv_bfloat16 hh=__float2bfloat16(v);
        g_aohi[ob+j]=hh;
        g_aolo[ob+j]=__float2bfloat16(v-__bfloat162float(hh));
    }
}

// ===== fused router =====
__global__ __launch_bounds__(256) void k_router(const float* __restrict__ rw, const float* __restrict__ rb){
    int n=blockIdx.x;
    int t=threadIdx.x, e=t>>5, lane=t&31;
    __shared__ float ms[DD];
    __shared__ float pe[EE];
    for(int i=t;i<DD;i+=256) ms[i]=g_m[(size_t)n*DD+i];
    g_moe[(size_t)n*DD+t]=0.f;
    g_moe[(size_t)n*DD+t+256]=0.f;
    __syncthreads();
    float s=0.f;
    for(int k=lane;k<DD;k+=32) s+=ms[k]*rw[k*EE+e];
    #pragma unroll
    for(int off=16;off>0;off>>=1) s+=__shfl_xor_sync(0xffffffffu,s,off);
    if(lane==0) pe[e]=s+rb[e];
    __syncthreads();
    if(t==0){
        float p[EE]; float mx=-1e30f;
        #pragma unroll
        for(int i=0;i<EE;i++){ p[i]=pe[i]; mx=fmaxf(mx,p[i]); }
        #pragma unroll
        for(int i=0;i<EE;i++) p[i]=__expf(p[i]-mx);
        int e1=0;
        for(int i=1;i<EE;i++) if(p[i]>p[e1]) e1=i;
        int e2=-1;
        for(int i=0;i<EE;i++) if(i!=e1 && (e2<0 || p[i]>p[e2])) e2=i;
        float den=p[e1]+p[e2];
        int pos=atomicAdd(&g_ecount[e1],1);
        g_elist[e1*NTOK+pos]=n; g_egate[e1*NTOK+pos]=p[e1]/den;
        pos=atomicAdd(&g_ecount[e2],1);
        g_elist[e2*NTOK+pos]=n; g_egate[e2*NTOK+pos]=p[e2]/den;
    }
}

// ===== host =====
extern "C" void kernel_launch(void* const* d_in, const int* in_sizes, int n_in,
                              void* d_out, int out_size){
    (void)in_sizes; (void)n_in; (void)out_size;
    const int*   ids  = (const int*)  d_in[0];
    const float* tok  = (const float*)d_in[1];
    const float* pos  = (const float*)d_in[2];
    const float* ln1g = (const float*)d_in[3];
    const float* ln1b = (const float*)d_in[4];
    const float* iqw  = (const float*)d_in[5];
    const float* iqb  = (const float*)d_in[6];
    const float* ikw  = (const float*)d_in[7];
    const float* ikb  = (const float*)d_in[8];
    const float* ihw  = (const float*)d_in[9];
    const float* wq   = (const float*)d_in[10];
    const float* bq   = (const float*)d_in[11];
    const float* wk   = (const float*)d_in[12];
    const float* bk   = (const float*)d_in[13];
    const float* wv   = (const float*)d_in[14];
    const float* bv   = (const float*)d_in[15];
    const float* wo   = (const float*)d_in[16];
    const float* bo   = (const float*)d_in[17];
    const float* ln2g = (const float*)d_in[18];
    const float* ln2b = (const float*)d_in[19];
    const float* rw   = (const float*)d_in[20];
    const float* rb   = (const float*)d_in[21];
    const float* ew1  = (const float*)d_in[22];
    const float* eb1  = (const float*)d_in[23];
    const float* ew2  = (const float*)d_in[24];
    const float* eb2  = (const float*)d_in[25];
    const float* lnfg = (const float*)d_in[26];
    const float* lnfb = (const float*)d_in[27];
    const float* ow   = (const float*)d_in[28];
    const float* ob   = (const float*)d_in[29];
    float* out = (float*)d_out;

    float *px,*ph,*pm,*pq,*pk,*pv,*pmoe,*pqi,*pki;
    int *pec;
    __nv_bfloat16 *phhi,*phlo,*pmhi,*pmlo,*powThi,*powTlo,*pw1Thi,*pw1Tlo,*pw2Thi,*pw2Tlo;
    __nv_bfloat16 *pwqh,*pwql,*pwkh,*pwkl,*pwvh,*pwvl,*pwoh,*pwol,*piqh,*piql,*pikh,*pikl;
    cudaGetSymbolAddress((void**)&px,g_x);
    cudaGetSymbolAddress((void**)&ph,g_h);
    cudaGetSymbolAddress((void**)&pm,g_m);
    cudaGetSymbolAddress((void**)&pq,g_q);
    cudaGetSymbolAddress((void**)&pk,g_k);
    cudaGetSymbolAddress((void**)&pv,g_v);
    cudaGetSymbolAddress((void**)&pmoe,g_moe);
    cudaGetSymbolAddress((void**)&pqi,g_qi);
    cudaGetSymbolAddress((void**)&pki,g_ki);
    cudaGetSymbolAddress((void**)&pec,g_ecount);
    cudaGetSymbolAddress((void**)&phhi,g_hhi);
    cudaGetSymbolAddress((void**)&phlo,g_hlo);
    cudaGetSymbolAddress((void**)&pmhi,g_mhi);
    cudaGetSymbolAddress((void**)&pmlo,g_mlo);
    cudaGetSymbolAddress((void**)&powThi,g_owThi);
    cudaGetSymbolAddress((void**)&powTlo,g_owTlo);
    cudaGetSymbolAddress((void**)&pw1Thi,g_w1Thi);
    cudaGetSymbolAddress((void**)&pw1Tlo,g_w1Tlo);
    cudaGetSymbolAddress((void**)&pw2Thi,g_w2Thi);
    cudaGetSymbolAddress((void**)&pw2Tlo,g_w2Tlo);
    cudaGetSymbolAddress((void**)&pwqh,g_wqThi);
    cudaGetSymbolAddress((void**)&pwql,g_wqTlo);
    cudaGetSymbolAddress((void**)&pwkh,g_wkThi);
    cudaGetSymbolAddress((void**)&pwkl,g_wkTlo);
    cudaGetSymbolAddress((void**)&pwvh,g_wvThi);
    cudaGetSymbolAddress((void**)&pwvl,g_wvTlo);
    cudaGetSymbolAddress((void**)&pwoh,g_woThi);
    cudaGetSymbolAddress((void**)&pwol,g_woTlo);
    cudaGetSymbolAddress((void**)&piqh,g_iqThi);
    cudaGetSymbolAddress((void**)&piql,g_iqTlo);
    cudaGetSymbolAddress((void**)&pikh,g_ikThi);
    cudaGetSymbolAddress((void**)&pikl,g_ikTlo);

    cudaFuncSetAttribute(k_hmma_vocab, cudaFuncAttributeMaxDynamicSharedMemorySize, V_TOTAL);
    cudaFuncSetAttribute(k_hmma_proj,  cudaFuncAttributeMaxDynamicSharedMemorySize, HS_TOTAL);
    cudaFuncSetAttribute(k_hmma_oproj, cudaFuncAttributeMaxDynamicSharedMemorySize, HS_TOTAL);
    cudaFuncSetAttribute(k_hmma_moe1,  cudaFuncAttributeMaxDynamicSharedMemorySize, HS_TOTAL);
    cudaFuncSetAttribute(k_hmma_moe2,  cudaFuncAttributeMaxDynamicSharedMemorySize, HS_TOTAL);

    k_transcvtB<<<dim3(VV/32, DD/64, 1),256>>>(ow, powThi, powTlo, DD, VV);
    k_transcvtB<<<dim3(FFD/32, DD/64, LLN*EE),256>>>(ew1, pw1Thi, pw1Tlo, DD, FFD);
    k_transcvtB<<<dim3(DD/32, FFD/64, LLN*EE),256>>>(ew2, pw2Thi, pw2Tlo, FFD, DD);
    k_transcvtB<<<dim3(DD/32, DD/64, LLN),256>>>(wq, pwqh, pwql, DD, DD);
    k_transcvtB<<<dim3(DD/32, DD/64, LLN),256>>>(wk, pwkh, pwkl, DD, DD);
    k_transcvtB<<<dim3(DD/32, DD/64, LLN),256>>>(wv, pwvh, pwvl, DD, DD);
    k_transcvtB<<<dim3(DD/32, DD/64, LLN),256>>>(wo, pwoh, pwol, DD, DD);
    k_transcvtB<<<dim3((HHI*DII)/32, DD/64, LLN),256>>>(iqw, piqh, piql, DD, HHI*DII);
    k_transcvtB<<<dim3((HHI*DII)/32, DD/64, LLN),256>>>(ikw, pikh, pikl, DD, HHI*DII);

    k_embed<<<NTOK,512>>>(ids, tok, pos);

    for(int l=0;l<LLN;l++){
        k_ln<<<NTOK,256>>>(px, ln1g+l*DD, ln1b+l*DD, ph, phhi, phlo,
                           (l>0)?pmoe:nullptr, nullptr);
        {   H3 p;
            p.h0=piqh+(size_t)l*HHI*DII*DD; p.l0=piql+(size_t)l*HHI*DII*DD; p.c0=iqb+l*HHI*DII; p.o0=pqi;
            p.h1=pikh+(size_t)l*HHI*DII*DD; p.l1=pikl+(size_t)l*HHI*DII*DD; p.c1=ikb+l*HHI*DII; p.o1=pki;
            p.h2=p.h0; p.l2=p.l0; p.c2=p.c0; p.o2=pqi;
            k_hmma_proj<<<dim3((HHI*DII)/128, NTOK/128, 2),256,HS_TOTAL>>>(p, HHI*DII);
        }
        k_idxscore<<<dim3(SSL/64,SSL/64,BB),256>>>(ihw+l*HHI);
        k_topk<<<dim3(SSL,BB),512>>>();
        {   H3 p;
            p.h0=pwqh+(size_t)l*DD*DD; p.l0=pwql+(size_t)l*DD*DD; p.c0=bq+l*DD; p.o0=pq;
            p.h1=pwkh+(size_t)l*DD*DD; p.l1=pwkl+(size_t)l*DD*DD; p.c1=bk+l*DD; p.o1=pk;
            p.h2=pwvh+(size_t)l*DD*DD; p.l2=pwvl+(size_t)l*DD*DD; p.c2=bv+l*DD; p.o2=pv;
            k_hmma_proj<<<dim3(DD/128, NTOK/128, 3),256,HS_TOTAL>>>(p, DD);
        }
        k_attn<<<dim3(SSL/16,HHN,BB),256>>>();
        k_hmma_oproj<<<dim3(DD/128, NTOK/128),256,HS_TOTAL>>>(
            pwoh+(size_t)l*DD*DD, pwol+(size_t)l*DD*DD, bo+l*DD, px);

        k_ln<<<NTOK,256>>>(px, ln2g+l*DD, ln2b+l*DD, pm, pmhi, pmlo, nullptr, pec);
        k_router<<<NTOK,256>>>(rw+(size_t)l*DD*EE, rb+l*EE);
        k_hmma_moe1<<<dim3(NTOK/128, FFD/128, EE),256,HS_TOTAL>>>(
            pw1Thi+(size_t)l*EE*FFD*DD, pw1Tlo+(size_t)l*EE*FFD*DD, eb1+(size_t)l*EE*FFD);
        k_hmma_moe2<<<dim3(NTOK/128, DD/128, EE),256,HS_TOTAL>>>(
            pw2Thi+(size_t)l*EE*DD*FFD, pw2Tlo+(size_t)l*EE*DD*FFD, eb2+(size_t)l*EE*DD);
    }

    k_ln<<<NTOK,256>>>(px, lnfg, lnfb, ph, phhi, phlo, pmoe, nullptr);
    k_hmma_vocab<<<dim3(NTOK/128, VV/256),256,V_TOTAL>>>(ob, out);
}

// round 15
// speedup vs baseline: 1.0430x; 1.0341x over previous
#include <cuda_runtime.h>
#include <cuda_bf16.h>
#include <math.h>
#include <stdint.h>

#define BB 2
#define SSL 1024
#define NTOK 2048
#define DD 512
#define HHN 8
#define HHI 4
#define DII 64
#define FFD 2048
#define EE 8
#define VV 32000
#define KTOP 256
#define NEGV (-1e9f)
#define EPSV 1e-5f
#define LLN 2
#define SCALE 0.125f

__device__ float g_x[NTOK*DD];
__device__ float g_h[NTOK*DD];
__device__ float g_m[NTOK*DD];
__device__ float g_q[NTOK*DD];
__device__ float g_k[NTOK*DD];
__device__ float g_v[NTOK*DD];
__device__ float g_moe[NTOK*DD];
__device__ float g_mask[(size_t)BB*SSL*SSL];
__device__ int g_ecount[EE];
__device__ int g_elist[EE*NTOK];
__device__ float g_egate[EE*NTOK];
__device__ alignas(16) __nv_bfloat16 g_hhi[NTOK*DD];
__device__ alignas(16) __nv_bfloat16 g_hlo[NTOK*DD];
__device__ alignas(16) __nv_bfloat16 g_mhi[NTOK*DD];
__device__ alignas(16) __nv_bfloat16 g_mlo[NTOK*DD];
__device__ alignas(16) __nv_bfloat16 g_aohi[NTOK*DD];
__device__ alignas(16) __nv_bfloat16 g_aolo[NTOK*DD];
__device__ alignas(16) float g_qi[NTOK*HHI*DII];
__device__ alignas(16) float g_ki[NTOK*HHI*DII];
__device__ alignas(16) __nv_bfloat16 g_owThi[(size_t)VV*DD];
__device__ alignas(16) __nv_bfloat16 g_owTlo[(size_t)VV*DD];
__device__ alignas(16) __nv_bfloat16 g_w1Thi[(size_t)LLN*EE*FFD*DD];
__device__ alignas(16) __nv_bfloat16 g_w1Tlo[(size_t)LLN*EE*FFD*DD];
__device__ alignas(16) __nv_bfloat16 g_w2Thi[(size_t)LLN*EE*DD*FFD];
__device__ alignas(16) __nv_bfloat16 g_w2Tlo[(size_t)LLN*EE*DD*FFD];
__device__ alignas(16) __nv_bfloat16 g_h1hi[(size_t)EE*NTOK*FFD];
__device__ alignas(16) __nv_bfloat16 g_h1lo[(size_t)EE*NTOK*FFD];
__device__ alignas(16) __nv_bfloat16 g_wqThi[LLN*DD*DD];
__device__ alignas(16) __nv_bfloat16 g_wqTlo[LLN*DD*DD];
__device__ alignas(16) __nv_bfloat16 g_wkThi[LLN*DD*DD];
__device__ alignas(16) __nv_bfloat16 g_wkTlo[LLN*DD*DD];
__device__ alignas(16) __nv_bfloat16 g_wvThi[LLN*DD*DD];
__device__ alignas(16) __nv_bfloat16 g_wvTlo[LLN*DD*DD];
__device__ alignas(16) __nv_bfloat16 g_woThi[LLN*DD*DD];
__device__ alignas(16) __nv_bfloat16 g_woTlo[LLN*DD*DD];
__device__ alignas(16) __nv_bfloat16 g_iqThi[LLN*HHI*DII*DD];
__device__ alignas(16) __nv_bfloat16 g_iqTlo[LLN*HHI*DII*DD];
__device__ alignas(16) __nv_bfloat16 g_ikThi[LLN*HHI*DII*DD];
__device__ alignas(16) __nv_bfloat16 g_ikTlo[LLN*HHI*DII*DD];

__device__ __forceinline__ float gelu_tanh(float x){
    float x3 = x*x*x;
    return 0.5f*x*(1.f + tanhf(0.7978845608028654f*(x + 0.044715f*x3)));
}

__global__ void k_embed(const int* __restrict__ ids, const float* __restrict__ tok, const float* __restrict__ pos){
    int n=blockIdx.x, t=threadIdx.x;
    g_x[(size_t)n*DD+t] = tok[(size_t)ids[n]*DD+t] + pos[(size_t)(n%SSL)*DD+t];
}

__global__ __launch_bounds__(256) void k_ln(float* __restrict__ in, const float* __restrict__ g,
        const float* __restrict__ b, float* __restrict__ out,
        __nv_bfloat16* __restrict__ hi, __nv_bfloat16* __restrict__ lo,
        const float* __restrict__ radd, int* __restrict__ ecz){
    int r=blockIdx.x, t=threadIdx.x;
    int lane=t&31, wid=t>>5;
    __shared__ float red1[8], red2[8];
    if(ecz && r==0 && t<EE) ecz[t]=0;
    float v0=in[(size_t)r*DD+t], v1=in[(size_t)r*DD+t+256];
    if(radd){
        v0 += radd[(size_t)r*DD+t];
        v1 += radd[(size_t)r*DD+t+256];
        in[(size_t)r*DD+t]=v0;
        in[(size_t)r*DD+t+256]=v1;
    }
    float s=v0+v1;
    #pragma unroll
    for(int off=16;off>0;off>>=1) s+=__shfl_xor_sync(0xffffffffu,s,off);
    if(lane==0) red1[wid]=s;
    __syncthreads();
    float mu=(red1[0]+red1[1]+red1[2]+red1[3]+red1[4]+red1[5]+red1[6]+red1[7])*(1.0f/DD);
    float d0=v0-mu, d1=v1-mu;
    float s2=d0*d0+d1*d1;
    #pragma unroll
    for(int off=16;off>0;off>>=1) s2+=__shfl_xor_sync(0xffffffffu,s2,off);
    if(lane==0) red2[wid]=s2;
    __syncthreads();
    float var=(red2[0]+red2[1]+red2[2]+red2[3]+red2[4]+red2[5]+red2[6]+red2[7])*(1.0f/DD);
    float rs=rsqrtf(var+EPSV);
    float o0=d0*rs*g[t]+b[t];
    float o1=d1*rs*g[t+256]+b[t+256];
    out[(size_t)r*DD+t]=o0;
    out[(size_t)r*DD+t+256]=o1;
    if(hi){
        __nv_bfloat16 h0=__float2bfloat16(o0), h1=__float2bfloat16(o1);
        hi[(size_t)r*DD+t]=h0;
        hi[(size_t)r*DD+t+256]=h1;
        lo[(size_t)r*DD+t]=__float2bfloat16(o0-__bfloat162float(h0));
        lo[(size_t)r*DD+t+256]=__float2bfloat16(o1-__bfloat162float(h1));
    }
}

__global__ __launch_bounds__(256) void k_transcvtB(const float* __restrict__ W,
        __nv_bfloat16* __restrict__ Thi, __nv_bfloat16* __restrict__ Tlo, int K, int N){
    int z=blockIdx.z;
    W   += (size_t)z*K*N;
    Thi += (size_t)z*N*K;
    Tlo += (size_t)z*N*K;
    __shared__ float t[32][66];
    int n0=blockIdx.x*32, k0=blockIdx.y*64;
    int lane=threadIdx.x&31, wid=threadIdx.x>>5;
    #pragma unroll
    for(int i=0;i<8;i++){
        int kk=wid*8+i;
        t[lane][kk]=W[(size_t)(k0+kk)*N + n0+lane];
    }
    __syncthreads();
    #pragma unroll
    for(int j=0;j<4;j++){
        int n=wid*4+j;
        float2 ab=*(float2*)&t[n][2*lane];
        __nv_bfloat16 ha=__float2bfloat16(ab.x), hb=__float2bfloat16(ab.y);
        uint32_t hw=(uint32_t)__bfloat16_as_ushort(ha) | ((uint32_t)__bfloat16_as_ushort(hb)<<16);
        __nv_bfloat16 la=__float2bfloat16(ab.x-__bfloat162float(ha));
        __nv_bfloat16 lb=__float2bfloat16(ab.y-__bfloat162float(hb));
        uint32_t lw=(uint32_t)__bfloat16_as_ushort(la) | ((uint32_t)__bfloat16_as_ushort(lb)<<16);
        *(uint32_t*)(Thi + (size_t)(n0+n)*K + k0 + 2*lane)=hw;
        *(uint32_t*)(Tlo + (size_t)(n0+n)*K + k0 + 2*lane)=lw;
    }
}

// ================= HMMA primitives =================
__device__ __forceinline__ uint32_t smem_u32(const void* p){
    uint32_t a;
    asm("{ .reg .u64 t; cvta.to.shared.u64 t, %1; cvt.u32.u64 %0, t; }" : "=r"(a) : "l"(p));
    return a;
}
__device__ __forceinline__ void ldsm4(uint32_t (&r)[4], uint32_t a){
    asm volatile("ldmatrix.sync.aligned.m8n8.x4.shared.b16 {%0,%1,%2,%3}, [%4];"
        : "=r"(r[0]),"=r"(r[1]),"=r"(r[2]),"=r"(r[3]) : "r"(a));
}
__device__ __forceinline__ void ldsm2(uint32_t (&r)[2], uint32_t a){
    asm volatile("ldmatrix.sync.aligned.m8n8.x2.shared.b16 {%0,%1}, [%2];"
        : "=r"(r[0]),"=r"(r[1]) : "r"(a));
}
__device__ __forceinline__ void mma16816(float (&c)[4], const uint32_t (&a)[4], const uint32_t (&b)[2]){
    asm volatile("mma.sync.aligned.m16n8k16.row.col.f32.bf16.bf16.f32 "
        "{%0,%1,%2,%3}, {%4,%5,%6,%7}, {%8,%9}, {%0,%1,%2,%3};"
        : "+f"(c[0]),"+f"(c[1]),"+f"(c[2]),"+f"(c[3])
        : "r"(a[0]),"r"(a[1]),"r"(a[2]),"r"(a[3]), "r"(b[0]),"r"(b[1]));
}
__device__ __forceinline__ void cpasync16(uint32_t dst, const void* src){
    asm volatile("{ .reg .u64 g; cvta.to.global.u64 g, %1; cp.async.ca.shared.global [%0], [g], 16; }"
        :: "r"(dst), "l"(src));
}
#define HS_BUF 24576
#define HS_TILE 6144
#define HS_TOTAL 49664

// register-staged double-buffered 128x128 mainloop (proven)
__device__ __forceinline__ void hmma_main(char* sm, const int* rowidx,
    const __nv_bfloat16* __restrict__ Ahi, const __nv_bfloat16* __restrict__ Alo, int sA,
    const __nv_bfloat16* __restrict__ Bhi, const __nv_bfloat16* __restrict__ Blo, int sB,
    int col0, int K, float (&acc)[4][4][4])
{
    int tid=threadIdx.x, lane=tid&31, warp=tid>>5;
    int wm=warp>>2, wn=warp&3;
    uint32_t smb = smem_u32(sm);
    #pragma unroll
    for(int i=0;i<4;i++)
        #pragma unroll
        for(int j=0;j<4;j++)
            #pragma unroll
            for(int q=0;q<4;q++) acc[i][j][q]=0.f;

    int ltile[4], lrow[4], lhalf[4];
    #pragma unroll
    for(int t=0;t<4;t++){
        int i = tid + t*256;
        ltile[t]=i>>8; lrow[t]=(i&255)>>1; lhalf[t]=(i&1)*8;
    }
    uint4 pre[4];
    const int NS = K>>4;
    int lb = lane&15;
    uint32_t boff = (uint32_t)((wn*32 + (lb&7))*48 + ((lb&8)?16:0));
    uint32_t aoff = (uint32_t)((wm*64 + (lane&7) + ((lane&8)?8:0))*48 + ((lane&16)?16:0));

    auto ldg = [&](int s){
        int k0 = s<<4;
        #pragma unroll
        for(int t=0;t<4;t++){
            const __nv_bfloat16* src;
            int row=lrow[t];
            if(ltile[t]==0)      src = Ahi + (size_t)rowidx[row]*sA;
            else if(ltile[t]==1) src = Alo + (size_t)rowidx[row]*sA;
            else if(ltile[t]==2) src = Bhi + (size_t)(col0+row)*sB;
            else                 src = Blo + (size_t)(col0+row)*sB;
            pre[t] = *(const uint4*)(src + k0 + lhalf[t]);
        }
    };
    auto sts = [&](int b){
        #pragma unroll
        for(int t=0;t<4;t++)
            *(uint4*)(sm + b*HS_BUF + ltile[t]*HS_TILE + lrow[t]*48 + lhalf[t]*2) = pre[t];
    };
    ldg(0); sts(0);
    __syncthreads();
    for(int s=0;s<NS;s++){
        int b=s&1;
        if(s+1<NS) ldg(s+1);
        uint32_t base = smb + b*HS_BUF;
        uint32_t bh[4][2], bl[4][2];
        #pragma unroll
        for(int j=0;j<4;j++){
            ldsm2(bh[j], base + 2*HS_TILE + boff + j*8*48);
            ldsm2(bl[j], base + 3*HS_TILE + boff + j*8*48);
        }
        #pragma unroll
        for(int i=0;i<4;i++){
            uint32_t a[4];
            ldsm4(a, base + aoff + i*16*48);
            #pragma unroll
            for(int j=0;j<4;j++){ mma16816(acc[i][j], a, bh[j]); mma16816(acc[i][j], a, bl[j]); }
            ldsm4(a, base + HS_TILE + aoff + i*16*48);
            #pragma unroll
            for(int j=0;j<4;j++) mma16816(acc[i][j], a, bh[j]);
        }
        if(s+1<NS) sts(b^1);
        __syncthreads();
    }
}

// ---- vocab: 128x256 tile, 3-stage cp.async pipeline; grid (NTOK/128, VV/256) ----
#define V_BUF 36864
#define V3_TOTAL 110592
__global__ __launch_bounds__(256,1) void k_hmma_vocab(const float* __restrict__ ob, float* __restrict__ out){
    extern __shared__ char sm[];
    int tid=threadIdx.x, lane=tid&31, warp=tid>>5;
    int wm=warp>>2, wn=warp&3;
    int row0=blockIdx.x*128, col0=blockIdx.y*256;
    uint32_t smb = smem_u32(sm);
    float acc[4][8][4];
    #pragma unroll
    for(int i=0;i<4;i++)
        #pragma unroll
        for(int j=0;j<8;j++)
            #pragma unroll
            for(int q=0;q<4;q++) acc[i][j][q]=0.f;

    auto load_stage = [&](int s, int b){
        int k0 = s<<4;
        #pragma unroll
        for(int c=0;c<6;c++){
            int i = tid + c*256;
            const __nv_bfloat16* src; uint32_t dst;
            if(i<512){
                int tile=i>>8, rem=i&255, row=rem>>1, half=(rem&1)*8;
                src = (tile? g_hlo : g_hhi) + (size_t)(row0+row)*DD + k0 + half;
                dst = smb + b*V_BUF + tile*6144 + row*48 + half*2;
            }else{
                int ii=i-512, tile=ii>>9, rem=ii&511, row=rem>>1, half=(rem&1)*8;
                src = (tile? g_owTlo : g_owThi) + (size_t)(col0+row)*DD + k0 + half;
                dst = smb + b*V_BUF + 12288 + tile*12288 + row*48 + half*2;
            }
            cpasync16(dst, src);
        }
        asm volatile("cp.async.commit_group;" ::: "memory");
    };
    const int NS = DD>>4;
    load_stage(0,0);
    load_stage(1,1);

    int lb = lane&15;
    uint32_t boff = (uint32_t)((wn*64 + (lb&7))*48 + ((lb&8)?16:0));
    uint32_t aoff = (uint32_t)((wm*64 + (lane&7) + ((lane&8)?8:0))*48 + ((lane&16)?16:0));
    int bs = 0;
    for(int s=0;s<NS;s++){
        asm volatile("cp.async.wait_group 1;" ::: "memory");
        __syncthreads();
        if(s+2<NS){
            int nb = bs+2; if(nb>=3) nb-=3;
            load_stage(s+2, nb);
        }
        uint32_t base = smb + bs*V_BUF;
        uint32_t bh[8][2], bl[8][2];
        #pragma unroll
        for(int j=0;j<8;j++){
            ldsm2(bh[j], base + 12288 + boff + j*8*48);
            ldsm2(bl[j], base + 24576 + boff + j*8*48);
        }
        #pragma unroll
        for(int i=0;i<4;i++){
            uint32_t a[4];
            ldsm4(a, base + aoff + i*16*48);
            #pragma unroll
            for(int j=0;j<8;j++){ mma16816(acc[i][j], a, bh[j]); mma16816(acc[i][j], a, bl[j]); }
            ldsm4(a, base + 6144 + aoff + i*16*48);
            #pragma unroll
            for(int j=0;j<8;j++) mma16816(acc[i][j], a, bh[j]);
        }
        __syncthreads();
        bs++; if(bs>=3) bs=0;
    }
    #pragma unroll
    for(int i=0;i<4;i++){
        int r0 = row0 + wm*64 + i*16 + (lane>>2);
        #pragma unroll
        for(int j=0;j<8;j++){
            int c = col0 + wn*64 + j*8 + (lane&3)*2;
            float b0=ob[c], b1=ob[c+1];
            out[(size_t)r0*VV + c]       = acc[i][j][0] + b0;
            out[(size_t)r0*VV + c+1]     = acc[i][j][1] + b1;
            out[(size_t)(r0+8)*VV + c]   = acc[i][j][2] + b0;
            out[(size_t)(r0+8)*VV + c+1] = acc[i][j][3] + b1;
        }
    }
}

// ---- merged projection: 5-way batched (idx_q, idx_k, Q, K, V), fp32 out ----
struct H5 {
    const __nv_bfloat16 *h[5], *l[5];
    const float *c[5];
    float *o[5];
    int N[5];
};
__global__ __launch_bounds__(256,1) void k_hmma_proj5(H5 p){
    int z=blockIdx.z;
    int N = p.N[z];
    int col0=blockIdx.x*128;
    if(col0>=N) return;
    extern __shared__ char sm[];
    int* rowidx = (int*)(sm + 2*HS_BUF);
    int tid=threadIdx.x;
    int row0=blockIdx.y*128;
    if(tid<128) rowidx[tid]=row0+tid;
    __syncthreads();
    float acc[4][4][4];
    hmma_main(sm, rowidx, g_hhi, g_hlo, DD, p.h[z], p.l[z], DD, col0, DD, acc);
    const float* bias = p.c[z];
    float* out = p.o[z];
    int lane=tid&31, warp=tid>>5, wm=warp>>2, wn=warp&3;
    #pragma unroll
    for(int i=0;i<4;i++){
        int r0 = row0 + wm*64 + i*16 + (lane>>2);
        #pragma unroll
        for(int j=0;j<4;j++){
            int c = col0 + wn*32 + j*8 + (lane&3)*2;
            float b0=bias[c], b1=bias[c+1];
            out[(size_t)r0*N + c]       = acc[i][j][0] + b0;
            out[(size_t)r0*N + c+1]     = acc[i][j][1] + b1;
            out[(size_t)(r0+8)*N + c]   = acc[i][j][2] + b0;
            out[(size_t)(r0+8)*N + c+1] = acc[i][j][3] + b1;
        }
    }
}

// ---- O projection with residual ----
__global__ __launch_bounds__(256,1) void k_hmma_oproj(const __nv_bfloat16* __restrict__ Whi,
        const __nv_bfloat16* __restrict__ Wlo, const float* __restrict__ bias, float* __restrict__ x){
    extern __shared__ char sm[];
    int* rowidx = (int*)(sm + 2*HS_BUF);
    int tid=threadIdx.x;
    int row0=blockIdx.y*128, col0=blockIdx.x*128;
    if(tid<128) rowidx[tid]=row0+tid;
    __syncthreads();
    float acc[4][4][4];
    hmma_main(sm, rowidx, g_aohi, g_aolo, DD, Whi, Wlo, DD, col0, DD, acc);
    int lane=tid&31, warp=tid>>5, wm=warp>>2, wn=warp&3;
    #pragma unroll
    for(int i=0;i<4;i++){
        int r0 = row0 + wm*64 + i*16 + (lane>>2);
        #pragma unroll
        for(int j=0;j<4;j++){
            int c = col0 + wn*32 + j*8 + (lane&3)*2;
            float b0=bias[c], b1=bias[c+1];
            x[(size_t)r0*DD + c]       += acc[i][j][0] + b0;
            x[(size_t)r0*DD + c+1]     += acc[i][j][1] + b1;
            x[(size_t)(r0+8)*DD + c]   += acc[i][j][2] + b0;
            x[(size_t)(r0+8)*DD + c+1] += acc[i][j][3] + b1;
        }
    }
}

// ---- MoE1: 128x128, gathered rows, GELU + split-bf16 out ----
__global__ __launch_bounds__(256,1) void k_hmma_moe1(const __nv_bfloat16* __restrict__ Whi,
        const __nv_bfloat16* __restrict__ Wlo, const float* __restrict__ B1){
    int e=blockIdx.z, cnt=g_ecount[e], row0=blockIdx.x*128;
    if(row0>=cnt) return;
    extern __shared__ char sm[];
    int* rowidx = (int*)(sm + 2*HS_BUF);
    int tid=threadIdx.x;
    int col0=blockIdx.y*128;
    if(tid<128){
        int r=row0+tid;
        rowidx[tid] = (r<cnt)? g_elist[e*NTOK+r] : g_elist[e*NTOK];
    }
    __syncthreads();
    float acc[4][4][4];
    hmma_main(sm, rowidx, g_mhi, g_mlo, DD,
              Whi+(size_t)e*FFD*DD, Wlo+(size_t)e*FFD*DD, DD, col0, DD, acc);
    const float* bia = B1 + (size_t)e*FFD;
    int lane=tid&31, warp=tid>>5, wm=warp>>2, wn=warp&3;
    #pragma unroll
    for(int i=0;i<4;i++){
        int r0 = row0 + wm*64 + i*16 + (lane>>2);
        #pragma unroll
        for(int j=0;j<4;j++){
            int c = col0 + wn*32 + j*8 + (lane&3)*2;
            float b0=bia[c], b1=bia[c+1];
            #pragma unroll
            for(int q=0;q<4;q++){
                int r = r0 + (q>=2?8:0);
                if(r>=cnt) continue;
                int cc = c + (q&1);
                float v = gelu_tanh(acc[i][j][q] + ((q&1)?b1:b0));
                __nv_bfloat16 h=__float2bfloat16(v);
                size_t o = ((size_t)e*NTOK + r)*FFD + cc;
                g_h1hi[o]=h; g_h1lo[o]=__float2bfloat16(v-__bfloat162float(h));
            }
        }
    }
}

// ---- MoE2: split-K=2, gated atomic scatter; grid (NTOK/128, DD/128, EE*2) ----
__global__ __launch_bounds__(256,1) void k_hmma_moe2(const __nv_bfloat16* __restrict__ Whi,
        const __nv_bfloat16* __restrict__ Wlo, const float* __restrict__ B2){
    int e=blockIdx.z>>1, sk=blockIdx.z&1;
    int cnt=g_ecount[e], row0=blockIdx.x*128;
    if(row0>=cnt) return;
    extern __shared__ char sm[];
    int* rowidx = (int*)(sm + 2*HS_BUF);
    int tid=threadIdx.x;
    int col0=blockIdx.y*128;
    int kbeg = sk*(FFD/2);
    if(tid<128) rowidx[tid] = e*NTOK + row0 + tid;
    __syncthreads();
    float acc[4][4][4];
    hmma_main(sm, rowidx, g_h1hi+kbeg, g_h1lo+kbeg, FFD,
              Whi+(size_t)e*DD*FFD+kbeg, Wlo+(size_t)e*DD*FFD+kbeg, FFD, col0, FFD/2, acc);
    const float* bia = B2 + (size_t)e*DD;
    int lane=tid&31, warp=tid>>5, wm=warp>>2, wn=warp&3;
    #pragma unroll
    for(int i=0;i<4;i++){
        int r0 = row0 + wm*64 + i*16 + (lane>>2);
        #pragma unroll
        for(int j=0;j<4;j++){
            int c = col0 + wn*32 + j*8 + (lane&3)*2;
            float b0 = sk? 0.f : bia[c];
            float b1 = sk? 0.f : bia[c+1];
            #pragma unroll
            for(int q=0;q<4;q++){
                int r = r0 + (q>=2?8:0);
                if(r>=cnt) continue;
                int tok=g_elist[e*NTOK+r];
                float gv=g_egate[e*NTOK+r];
                int cc = c + (q&1);
                atomicAdd(&g_moe[(size_t)tok*DD+cc], gv*(acc[i][j][q] + ((q&1)?b1:b0)));
            }
        }
    }
}

// ===== indexer scores (causal tile-skip) =====
__global__ __launch_bounds__(256) void k_idxscore(const float* __restrict__ hw){
    int kt=blockIdx.x, qt=blockIdx.y, b=blockIdx.z;
    int tx=threadIdx.x&15, ty=threadIdx.x>>4;
    if(kt>qt){
        #pragma unroll
        for(int i=0;i<4;i++){
            int q=qt*64+ty*4+i;
            float4 nv={NEGV,NEGV,NEGV,NEGV};
            *(float4*)&g_mask[((size_t)b*SSL+q)*SSL + kt*64+tx*4]=nv;
        }
        return;
    }
    __shared__ float Qs[64][68];
    __shared__ float Ks[64][68];
    float acc[4][4]={};
    for(int h=0;h<HHI;h++){
        for(int i=threadIdx.x;i<4096;i+=256){
            int r=i>>6, d=i&63;
            Qs[d][r]=g_qi[(size_t)(b*SSL+qt*64+r)*(HHI*DII)+h*64+d];
            Ks[d][r]=g_ki[(size_t)(b*SSL+kt*64+r)*(HHI*DII)+h*64+d];
        }
        __syncthreads();
        float w=hw[h];
        float dot[4][4]={};
        #pragma unroll 8
        for(int d=0;d<64;d++){
            float4 a4=*(const float4*)&Qs[d][ty*4];
            float4 b4=*(const float4*)&Ks[d][tx*4];
            float a[4]={a4.x,a4.y,a4.z,a4.w};
            float bb[4]={b4.x,b4.y,b4.z,b4.w};
            #pragma unroll
            for(int i=0;i<4;i++)
                #pragma unroll
                for(int j=0;j<4;j++) dot[i][j]+=a[i]*bb[j];
        }
        #pragma unroll
        for(int i=0;i<4;i++)
            #pragma unroll
            for(int j=0;j<4;j++) acc[i][j]+=fmaxf(dot[i][j],0.f)*w;
        __syncthreads();
    }
    #pragma unroll
    for(int i=0;i<4;i++){
        int q=qt*64+ty*4+i;
        #pragma unroll
        for(int j=0;j<4;j++){
            int k=kt*64+tx*4+j;
            g_mask[((size_t)b*SSL+q)*SSL+k]=acc[i][j]+((k<=q)?0.f:NEGV);
        }
    }
}

// ===== top-K =====
__global__ __launch_bounds__(512) void k_topk(){
    int q=blockIdx.x, b=blockIdx.y, t=threadIdx.x;
    size_t base=((size_t)b*SSL+q)*SSL;
    if(q < KTOP){
        for(int k=t;k<SSL;k+=512)
            g_mask[base+k]=(k<=q)?0.f:NEGV;
        return;
    }
    __shared__ float s[1024];
    s[t]=g_mask[base+t];
    s[t+512]=g_mask[base+t+512];
    __syncthreads();
    for(int size=2;size<=1024;size<<=1){
        for(int stride=size>>1;stride>0;stride>>=1){
            int lo=2*stride*(t/stride)+(t%stride);
            int hi=lo+stride;
            bool desc=((lo&size)==0);
            float a=s[lo], bv=s[hi];
            if((a<bv)==desc){ s[lo]=bv; s[hi]=a; }
            __syncthreads();
        }
    }
    float thr=s[KTOP-1];
    for(int k=t;k<SSL;k+=512){
        float v=g_mask[base+k];
        g_mask[base+k]=(k<=q && v>=thr)?0.f:NEGV;
    }
}

// ===== attention =====
__global__ __launch_bounds__(256) void k_attn(){
    int qt=blockIdx.x, h=blockIdx.y, b=blockIdx.z;
    int t=threadIdx.x, row=t>>4, cg=t&15;
    __shared__ float qs[16][68];
    __shared__ float Ks[64][68];
    __shared__ float Vs[64][68];
    __shared__ float Sc[16][68];
    __shared__ float mrow[16], lrow[16];
    int q0=qt*16;
    {
        int r=t>>4, d4=(t&15)*4;
        *(float4*)&qs[r][d4] = *(const float4*)&g_q[(size_t)(b*SSL+q0+r)*DD+h*64+d4];
    }
    if(t<16){ mrow[t]=-1e30f; lrow[t]=0.f; }
    float oacc[4]={0.f,0.f,0.f,0.f};
    __syncthreads();
    const float* maskrow=g_mask+((size_t)b*SSL+(q0+row))*SSL;
    int kmax = q0 + 16;
    for(int k0=0;k0<kmax;k0+=64){
        #pragma unroll
        for(int c=0;c<4;c++){
            int i = t + c*256;
            int r=i>>4, d4=(i&15)*4;
            *(float4*)&Ks[r][d4] = *(const float4*)&g_k[(size_t)(b*SSL+k0+r)*DD+h*64+d4];
            *(float4*)&Vs[r][d4] = *(const float4*)&g_v[(size_t)(b*SSL+k0+r)*DD+h*64+d4];
        }
        __syncthreads();
        float sv[4]={0.f,0.f,0.f,0.f};
        #pragma unroll
        for(int d0=0;d0<64;d0+=4){
            float4 q4=*(const float4*)&qs[row][d0];
            #pragma unroll
            for(int j=0;j<4;j++){
                float4 k4=*(const float4*)&Ks[j*16+cg][d0];
                sv[j]+=q4.x*k4.x+q4.y*k4.y+q4.z*k4.z+q4.w*k4.w;
            }
        }
        #pragma unroll
        for(int j=0;j<4;j++) sv[j]=sv[j]*SCALE+maskrow[k0+j*16+cg];
        float mold=mrow[row], lold=lrow[row];
        float tmax=fmaxf(fmaxf(sv[0],sv[1]),fmaxf(sv[2],sv[3]));
        tmax=fmaxf(tmax,mold);
        #pragma unroll
        for(int off=8;off>0;off>>=1) tmax=fmaxf(tmax,__shfl_xor_sync(0xffffffffu,tmax,off,16));
        float c=__expf(mold-tmax);
        float lsum=0.f;
        #pragma unroll
        for(int j=0;j<4;j++){
            float p=__expf(sv[j]-tmax);
            Sc[row][j*16+cg]=p;
            lsum+=p;
        }
        #pragma unroll
        for(int off=8;off>0;off>>=1) lsum+=__shfl_xor_sync(0xffffffffu,lsum,off,16);
        if(cg==0){ mrow[row]=tmax; lrow[row]=lold*c+lsum; }
        __syncwarp();
        #pragma unroll
        for(int j=0;j<4;j++) oacc[j]*=c;
        #pragma unroll
        for(int k=0;k<64;k++){
            float s=Sc[row][k];
            float4 v4=*(const float4*)&Vs[k][cg*4];
            oacc[0]+=s*v4.x; oacc[1]+=s*v4.y; oacc[2]+=s*v4.z; oacc[3]+=s*v4.w;
        }
        __syncthreads();
    }
    float linv=1.0f/lrow[row];
    size_t ob = (size_t)(b*SSL+q0+row)*DD + h*64 + cg*4;
    #pragma unroll
    for(int j=0;j<4;j++){
        float v = oacc[j]*linv;
        __nv_bfloat16 hh=__float2bfloat16(v);
        g_aohi[ob+j]=hh;
        g_aolo[ob+j]=__float2bfloat16(v-__bfloat162float(hh));
    }
}

// ===== fused router =====
__global__ __launch_bounds__(256) void k_router(const float* __restrict__ rw, const float* __restrict__ rb){
    int n=blockIdx.x;
    int t=threadIdx.x, e=t>>5, lane=t&31;
    __shared__ float ms[DD];
    __shared__ float pe[EE];
    for(int i=t;i<DD;i+=256) ms[i]=g_m[(size_t)n*DD+i];
    g_moe[(size_t)n*DD+t]=0.f;
    g_moe[(size_t)n*DD+t+256]=0.f;
    __syncthreads();
    float s=0.f;
    for(int k=lane;k<DD;k+=32) s+=ms[k]*rw[k*EE+e];
    #pragma unroll
    for(int off=16;off>0;off>>=1) s+=__shfl_xor_sync(0xffffffffu,s,off);
    if(lane==0) pe[e]=s+rb[e];
    __syncthreads();
    if(t==0){
        float p[EE]; float mx=-1e30f;
        #pragma unroll
        for(int i=0;i<EE;i++){ p[i]=pe[i]; mx=fmaxf(mx,p[i]); }
        #pragma unroll
        for(int i=0;i<EE;i++) p[i]=__expf(p[i]-mx);
        int e1=0;
        for(int i=1;i<EE;i++) if(p[i]>p[e1]) e1=i;
        int e2=-1;
        for(int i=0;i<EE;i++) if(i!=e1 && (e2<0 || p[i]>p[e2])) e2=i;
        float den=p[e1]+p[e2];
        int pos=atomicAdd(&g_ecount[e1],1);
        g_elist[e1*NTOK+pos]=n; g_egate[e1*NTOK+pos]=p[e1]/den;
        pos=atomicAdd(&g_ecount[e2],1);
        g_elist[e2*NTOK+pos]=n; g_egate[e2*NTOK+pos]=p[e2]/den;
    }
}

// ===== host =====
extern "C" void kernel_launch(void* const* d_in, const int* in_sizes, int n_in,
                              void* d_out, int out_size){
    (void)in_sizes; (void)n_in; (void)out_size;
    const int*   ids  = (const int*)  d_in[0];
    const float* tok  = (const float*)d_in[1];
    const float* pos  = (const float*)d_in[2];
    const float* ln1g = (const float*)d_in[3];
    const float* ln1b = (const float*)d_in[4];
    const float* iqw  = (const float*)d_in[5];
    const float* iqb  = (const float*)d_in[6];
    const float* ikw  = (const float*)d_in[7];
    const float* ikb  = (const float*)d_in[8];
    const float* ihw  = (const float*)d_in[9];
    const float* wq   = (const float*)d_in[10];
    const float* bq   = (const float*)d_in[11];
    const float* wk   = (const float*)d_in[12];
    const float* bk   = (const float*)d_in[13];
    const float* wv   = (const float*)d_in[14];
    const float* bv   = (const float*)d_in[15];
    const float* wo   = (const float*)d_in[16];
    const float* bo   = (const float*)d_in[17];
    const float* ln2g = (const float*)d_in[18];
    const float* ln2b = (const float*)d_in[19];
    const float* rw   = (const float*)d_in[20];
    const float* rb   = (const float*)d_in[21];
    const float* ew1  = (const float*)d_in[22];
    const float* eb1  = (const float*)d_in[23];
    const float* ew2  = (const float*)d_in[24];
    const float* eb2  = (const float*)d_in[25];
    const float* lnfg = (const float*)d_in[26];
    const float* lnfb = (const float*)d_in[27];
    const float* ow   = (const float*)d_in[28];
    const float* ob   = (const float*)d_in[29];
    float* out = (float*)d_out;

    float *px,*ph,*pm,*pq,*pk,*pv,*pmoe,*pqi,*pki;
    int *pec;
    __nv_bfloat16 *phhi,*phlo,*pmhi,*pmlo,*powThi,*powTlo,*pw1Thi,*pw1Tlo,*pw2Thi,*pw2Tlo;
    __nv_bfloat16 *pwqh,*pwql,*pwkh,*pwkl,*pwvh,*pwvl,*pwoh,*pwol,*piqh,*piql,*pikh,*pikl;
    cudaGetSymbolAddress((void**)&px,g_x);
    cudaGetSymbolAddress((void**)&ph,g_h);
    cudaGetSymbolAddress((void**)&pm,g_m);
    cudaGetSymbolAddress((void**)&pq,g_q);
    cudaGetSymbolAddress((void**)&pk,g_k);
    cudaGetSymbolAddress((void**)&pv,g_v);
    cudaGetSymbolAddress((void**)&pmoe,g_moe);
    cudaGetSymbolAddress((void**)&pqi,g_qi);
    cudaGetSymbolAddress((void**)&pki,g_ki);
    cudaGetSymbolAddress((void**)&pec,g_ecount);
    cudaGetSymbolAddress((void**)&phhi,g_hhi);
    cudaGetSymbolAddress((void**)&phlo,g_hlo);
    cudaGetSymbolAddress((void**)&pmhi,g_mhi);
    cudaGetSymbolAddress((void**)&pmlo,g_mlo);
    cudaGetSymbolAddress((void**)&powThi,g_owThi);
    cudaGetSymbolAddress((void**)&powTlo,g_owTlo);
    cudaGetSymbolAddress((void**)&pw1Thi,g_w1Thi);
    cudaGetSymbolAddress((void**)&pw1Tlo,g_w1Tlo);
    cudaGetSymbolAddress((void**)&pw2Thi,g_w2Thi);
    cudaGetSymbolAddress((void**)&pw2Tlo,g_w2Tlo);
    cudaGetSymbolAddress((void**)&pwqh,g_wqThi);
    cudaGetSymbolAddress((void**)&pwql,g_wqTlo);
    cudaGetSymbolAddress((void**)&pwkh,g_wkThi);
    cudaGetSymbolAddress((void**)&pwkl,g_wkTlo);
    cudaGetSymbolAddress((void**)&pwvh,g_wvThi);
    cudaGetSymbolAddress((void**)&pwvl,g_wvTlo);
    cudaGetSymbolAddress((void**)&pwoh,g_woThi);
    cudaGetSymbolAddress((void**)&pwol,g_woTlo);
    cudaGetSymbolAddress((void**)&piqh,g_iqThi);
    cudaGetSymbolAddress((void**)&piql,g_iqTlo);
    cudaGetSymbolAddress((void**)&pikh,g_ikThi);
    cudaGetSymbolAddress((void**)&pikl,g_ikTlo);

    cudaFuncSetAttribute(k_hmma_vocab, cudaFuncAttributeMaxDynamicSharedMemorySize, V3_TOTAL);
    cudaFuncSetAttribute(k_hmma_proj5, cudaFuncAttributeMaxDynamicSharedMemorySize, HS_TOTAL);
    cudaFuncSetAttribute(k_hmma_oproj, cudaFuncAttributeMaxDynamicSharedMemorySize, HS_TOTAL);
    cudaFuncSetAttribute(k_hmma_moe1,  cudaFuncAttributeMaxDynamicSharedMemorySize, HS_TOTAL);
    cudaFuncSetAttribute(k_hmma_moe2,  cudaFuncAttributeMaxDynamicSharedMemorySize, HS_TOTAL);

    k_transcvtB<<<dim3(VV/32, DD/64, 1),256>>>(ow, powThi, powTlo, DD, VV);
    k_transcvtB<<<dim3(FFD/32, DD/64, LLN*EE),256>>>(ew1, pw1Thi, pw1Tlo, DD, FFD);
    k_transcvtB<<<dim3(DD/32, FFD/64, LLN*EE),256>>>(ew2, pw2Thi, pw2Tlo, FFD, DD);
    k_transcvtB<<<dim3(DD/32, DD/64, LLN),256>>>(wq, pwqh, pwql, DD, DD);
    k_transcvtB<<<dim3(DD/32, DD/64, LLN),256>>>(wk, pwkh, pwkl, DD, DD);
    k_transcvtB<<<dim3(DD/32, DD/64, LLN),256>>>(wv, pwvh, pwvl, DD, DD);
    k_transcvtB<<<dim3(DD/32, DD/64, LLN),256>>>(wo, pwoh, pwol, DD, DD);
    k_transcvtB<<<dim3((HHI*DII)/32, DD/64, LLN),256>>>(iqw, piqh, piql, DD, HHI*DII);
    k_transcvtB<<<dim3((HHI*DII)/32, DD/64, LLN),256>>>(ikw, pikh, pikl, DD, HHI*DII);

    k_embed<<<NTOK,512>>>(ids, tok, pos);

    for(int l=0;l<LLN;l++){
        k_ln<<<NTOK,256>>>(px, ln1g+l*DD, ln1b+l*DD, ph, phhi, phlo,
                           (l>0)?pmoe:nullptr, nullptr);
        {   // merged idx_q/idx_k/Q/K/V projections (z=5)
            H5 p;
            p.h[0]=piqh+(size_t)l*HHI*DII*DD; p.l[0]=piql+(size_t)l*HHI*DII*DD; p.c[0]=iqb+l*HHI*DII; p.o[0]=pqi; p.N[0]=HHI*DII;
            p.h[1]=pikh+(size_t)l*HHI*DII*DD; p.l[1]=pikl+(size_t)l*HHI*DII*DD; p.c[1]=ikb+l*HHI*DII; p.o[1]=pki; p.N[1]=HHI*DII;
            p.h[2]=pwqh+(size_t)l*DD*DD; p.l[2]=pwql+(size_t)l*DD*DD; p.c[2]=bq+l*DD; p.o[2]=pq; p.N[2]=DD;
            p.h[3]=pwkh+(size_t)l*DD*DD; p.l[3]=pwkl+(size_t)l*DD*DD; p.c[3]=bk+l*DD; p.o[3]=pk; p.N[3]=DD;
            p.h[4]=pwvh+(size_t)l*DD*DD; p.l[4]=pwvl+(size_t)l*DD*DD; p.c[4]=bv+l*DD; p.o[4]=pv; p.N[4]=DD;
            k_hmma_proj5<<<dim3(DD/128, NTOK/128, 5),256,HS_TOTAL>>>(p);
        }
        k_idxscore<<<dim3(SSL/64,SSL/64,BB),256>>>(ihw+l*HHI);
        k_topk<<<dim3(SSL,BB),512>>>();
        k_attn<<<dim3(SSL/16,HHN,BB),256>>>();
        k_hmma_oproj<<<dim3(DD/128, NTOK/128),256,HS_TOTAL>>>(
            pwoh+(size_t)l*DD*DD, pwol+(size_t)l*DD*DD, bo+l*DD, px);

        k_ln<<<NTOK,256>>>(px, ln2g+l*DD, ln2b+l*DD, pm, pmhi, pmlo, nullptr, pec);
        k_router<<<NTOK,256>>>(rw+(size_t)l*DD*EE, rb+l*EE);
        k_hmma_moe1<<<dim3(NTOK/128, FFD/128, EE),256,HS_TOTAL>>>(
            pw1Thi+(size_t)l*EE*FFD*DD, pw1Tlo+(size_t)l*EE*FFD*DD, eb1+(size_t)l*EE*FFD);
        k_hmma_moe2<<<dim3(NTOK/128, DD/128, EE*2),256,HS_TOTAL>>>(
            pw2Thi+(size_t)l*EE*DD*FFD, pw2Tlo+(size_t)l*EE*DD*FFD, eb2+(size_t)l*EE*DD);
    }

    k_ln<<<NTOK,256>>>(px, lnfg, lnfb, ph, phhi, phlo, pmoe, nullptr);
    k_hmma_vocab<<<dim3(NTOK/128, VV/256),256,V3_TOTAL>>>(ob, out);
}